// round 4
// baseline (speedup 1.0000x reference)
#include <cuda_runtime.h>
#include <math.h>

// Problem dims
#define NN 50000
#define EE 800000
#define ET 850000      // EE + NN self-loops
#define FIN 128
#define H1C1 256       // 4 heads * 64
#define C2 128
#define NG 32
#define NCLS 5
#define NEG_SLOPE 0.2f

// ---------------- scratch (device globals; no allocations allowed) --------
__device__ float g_h1[(size_t)NN * H1C1];     // x @ W1
__device__ float g_out1[(size_t)NN * H1C1];   // elu(gat1)
__device__ float g_h2[(size_t)NN * C2];       // out1 @ W2
__device__ float g_out2[(size_t)NN * C2];     // elu(gat2)
__device__ float g_asrc1[NN * 4], g_adst1[NN * 4];
__device__ float g_asrc2[NN], g_adst2[NN];
__device__ int   g_deg[NN];
__device__ int   g_rowptr[NN + 1];
__device__ int   g_cursor[NN];
__device__ int   g_csrsrc[ET];
__device__ float g_pool[NG * C2];
__device__ int   g_counts[NG];
__device__ int   g_is64;                      // index dtype flag (1 = int64, 0 = int32)

// ---------------- utility -------------------------------------------------
__device__ __forceinline__ float lrelu(float x) { return x > 0.f ? x : NEG_SLOPE * x; }
__device__ __forceinline__ float elu(float x)   { return x > 0.f ? x : (expf(x) - 1.f); }

// Read index i from an array that is either int32 or int64 (per g_is64 flag).
__device__ __forceinline__ int ld_idx(const void* p, long long i, int is64) {
    if (is64) return (int)((const long long*)p)[i];
    return ((const int*)p)[i];
}

// ---------------- dtype detection ------------------------------------------
// If indices are int64 (values < 2^31), every high 32-bit word is 0.
// If int32, the odd words are random node ids; OR over 128 of them is nonzero
// with overwhelming probability.
__global__ void detect_kernel(const unsigned int* __restrict__ w) {
    if (threadIdx.x == 0) {
        unsigned int nz = 0;
        for (int i = 0; i < 128; i++) nz |= w[2 * i + 1];
        g_is64 = (nz == 0u) ? 1 : 0;
    }
}

// ---------------- zero init -----------------------------------------------
__global__ void zero_kernel() {
    int i = blockIdx.x * blockDim.x + threadIdx.x;
    if (i < NN) g_deg[i] = 0;
    if (i < NG * C2) g_pool[i] = 0.f;
    if (i < NG) g_counts[i] = 0;
}

// ---------------- SGEMM: C[M,Nn] = A[M,K] * B[K,Nn] ------------------------
// 64x64 tile, BK=16, 256 threads, 4x4 per-thread register tile.
__global__ void sgemm64(const float* __restrict__ A, const float* __restrict__ B,
                        float* __restrict__ C, int M, int Nn, int K) {
    __shared__ __align__(16) float As[16][65];
    __shared__ __align__(16) float Bs[16][64];
    int tid = threadIdx.x;
    int tx = tid & 15, ty = tid >> 4;
    int m0 = blockIdx.x * 64, n0 = blockIdx.y * 64;

    float acc[4][4];
#pragma unroll
    for (int i = 0; i < 4; i++)
#pragma unroll
        for (int j = 0; j < 4; j++) acc[i][j] = 0.f;

    int arow = m0 + (tid >> 2);
    int acol = (tid & 3) * 4;
    int brow = tid >> 4;          // 0..15
    int bcol = (tid & 15) * 4;

    for (int kt = 0; kt < K; kt += 16) {
        float4 av = (arow < M)
            ? *(const float4*)(A + (size_t)arow * K + kt + acol)
            : make_float4(0.f, 0.f, 0.f, 0.f);
        As[acol + 0][tid >> 2] = av.x;
        As[acol + 1][tid >> 2] = av.y;
        As[acol + 2][tid >> 2] = av.z;
        As[acol + 3][tid >> 2] = av.w;
        *(float4*)&Bs[brow][bcol] = *(const float4*)(B + (size_t)(kt + brow) * Nn + n0 + bcol);
        __syncthreads();
#pragma unroll
        for (int k = 0; k < 16; k++) {
            float a0 = As[k][ty * 4 + 0];
            float a1 = As[k][ty * 4 + 1];
            float a2 = As[k][ty * 4 + 2];
            float a3 = As[k][ty * 4 + 3];
            float4 b = *(float4*)&Bs[k][tx * 4];
            acc[0][0] += a0 * b.x; acc[0][1] += a0 * b.y; acc[0][2] += a0 * b.z; acc[0][3] += a0 * b.w;
            acc[1][0] += a1 * b.x; acc[1][1] += a1 * b.y; acc[1][2] += a1 * b.z; acc[1][3] += a1 * b.w;
            acc[2][0] += a2 * b.x; acc[2][1] += a2 * b.y; acc[2][2] += a2 * b.z; acc[2][3] += a2 * b.w;
            acc[3][0] += a3 * b.x; acc[3][1] += a3 * b.y; acc[3][2] += a3 * b.z; acc[3][3] += a3 * b.w;
        }
        __syncthreads();
    }
#pragma unroll
    for (int i = 0; i < 4; i++) {
        int r = m0 + ty * 4 + i;
        if (r < M) {
            float4 o = make_float4(acc[i][0], acc[i][1], acc[i][2], acc[i][3]);
            *(float4*)(C + (size_t)r * Nn + n0 + tx * 4) = o;
        }
    }
}

// ---------------- attention coefficients (layer 1, 4 heads x 64) ----------
__global__ void attn_coef1(const float* __restrict__ att_src, const float* __restrict__ att_dst) {
    int warp = (blockIdx.x * blockDim.x + threadIdx.x) >> 5;
    if (warp >= NN) return;
    int lane = threadIdx.x & 31;
    int head = lane >> 3;
    int lc = (lane & 7) * 8;
    const float* hrow = g_h1 + (size_t)warp * H1C1 + head * 64 + lc;
    float4 h0 = *(const float4*)hrow;
    float4 h1v = *(const float4*)(hrow + 4);
    const float* as_ = att_src + head * 64 + lc;
    const float* ad_ = att_dst + head * 64 + lc;
    float s = h0.x * as_[0] + h0.y * as_[1] + h0.z * as_[2] + h0.w * as_[3]
            + h1v.x * as_[4] + h1v.y * as_[5] + h1v.z * as_[6] + h1v.w * as_[7];
    float d = h0.x * ad_[0] + h0.y * ad_[1] + h0.z * ad_[2] + h0.w * ad_[3]
            + h1v.x * ad_[4] + h1v.y * ad_[5] + h1v.z * ad_[6] + h1v.w * ad_[7];
#pragma unroll
    for (int off = 4; off; off >>= 1) {
        s += __shfl_xor_sync(0xffffffffu, s, off);
        d += __shfl_xor_sync(0xffffffffu, d, off);
    }
    if ((lane & 7) == 0) {
        g_asrc1[warp * 4 + head] = s;
        g_adst1[warp * 4 + head] = d;
    }
}

// ---------------- attention coefficients (layer 2, 1 head x 128) ----------
__global__ void attn_coef2(const float* __restrict__ att_src, const float* __restrict__ att_dst) {
    int warp = (blockIdx.x * blockDim.x + threadIdx.x) >> 5;
    if (warp >= NN) return;
    int lane = threadIdx.x & 31;
    const float* hrow = g_h2 + (size_t)warp * C2 + lane * 4;
    float4 h = *(const float4*)hrow;
    const float* as_ = att_src + lane * 4;
    const float* ad_ = att_dst + lane * 4;
    float s = h.x * as_[0] + h.y * as_[1] + h.z * as_[2] + h.w * as_[3];
    float d = h.x * ad_[0] + h.y * ad_[1] + h.z * ad_[2] + h.w * ad_[3];
#pragma unroll
    for (int off = 16; off; off >>= 1) {
        s += __shfl_xor_sync(0xffffffffu, s, off);
        d += __shfl_xor_sync(0xffffffffu, d, off);
    }
    if (lane == 0) { g_asrc2[warp] = s; g_adst2[warp] = d; }
}

// ---------------- CSR build -------------------------------------------------
__global__ void degree_kernel(const void* __restrict__ ei) {
    int e = blockIdx.x * blockDim.x + threadIdx.x;
    if (e >= ET) return;
    int is64 = g_is64;
    int d = (e < EE) ? ld_idx(ei, (long long)EE + e, is64) : (e - EE);
    atomicAdd(&g_deg[d], 1);
}

// single-block exclusive scan over g_deg -> g_rowptr, g_cursor
__global__ void scan_kernel() {
    __shared__ int ssum[1024];
    int t = threadIdx.x;
    const int CH = (NN + 1023) / 1024;   // 49
    int begin = t * CH;
    int lim = begin + CH < NN ? begin + CH : NN;
    int s = 0;
    for (int i = begin; i < lim; i++) s += g_deg[i];
    ssum[t] = s;
    __syncthreads();
    // inclusive scan (Hillis-Steele)
    for (int off = 1; off < 1024; off <<= 1) {
        int v = (t >= off) ? ssum[t - off] : 0;
        __syncthreads();
        ssum[t] += v;
        __syncthreads();
    }
    int run = ssum[t] - s;   // exclusive prefix for this chunk
    for (int i = begin; i < lim; i++) {
        g_rowptr[i] = run;
        g_cursor[i] = run;
        run += g_deg[i];
    }
    if (t == 1023) g_rowptr[NN] = ssum[1023];
}

__global__ void scatter_kernel(const void* __restrict__ ei) {
    int e = blockIdx.x * blockDim.x + threadIdx.x;
    if (e >= ET) return;
    int is64 = g_is64;
    int s, d;
    if (e < EE) { s = ld_idx(ei, e, is64); d = ld_idx(ei, (long long)EE + e, is64); }
    else        { s = e - EE;              d = e - EE; }
    int pos = atomicAdd(&g_cursor[d], 1);
    g_csrsrc[pos] = s;
}

// ---------------- layer-1 aggregation: warp per dst node ------------------
// out1[dst] = elu( sum_e softmax(alpha_e) * h1[src_e] + b1 )
__global__ void aggregate1(const float* __restrict__ b1) {
    int warp = (blockIdx.x * blockDim.x + threadIdx.x) >> 5;
    if (warp >= NN) return;
    int lane = threadIdx.x & 31;
    int head = lane >> 3;
    int start = g_rowptr[warp], end = g_rowptr[warp + 1];
    float4 ad4 = *(const float4*)(g_adst1 + warp * 4);

    // pass 1: per-head max over incoming edges
    float m0 = -1e30f, m1 = -1e30f, m2 = -1e30f, m3 = -1e30f;
    for (int i = start + lane; i < end; i += 32) {
        int s = g_csrsrc[i];
        float4 as4 = *(const float4*)(g_asrc1 + s * 4);
        m0 = fmaxf(m0, lrelu(as4.x + ad4.x));
        m1 = fmaxf(m1, lrelu(as4.y + ad4.y));
        m2 = fmaxf(m2, lrelu(as4.z + ad4.z));
        m3 = fmaxf(m3, lrelu(as4.w + ad4.w));
    }
#pragma unroll
    for (int off = 16; off; off >>= 1) {
        m0 = fmaxf(m0, __shfl_xor_sync(0xffffffffu, m0, off));
        m1 = fmaxf(m1, __shfl_xor_sync(0xffffffffu, m1, off));
        m2 = fmaxf(m2, __shfl_xor_sync(0xffffffffu, m2, off));
        m3 = fmaxf(m3, __shfl_xor_sync(0xffffffffu, m3, off));
    }
    float mh = (head == 0) ? m0 : (head == 1) ? m1 : (head == 2) ? m2 : m3;
    float ad = (head == 0) ? ad4.x : (head == 1) ? ad4.y : (head == 2) ? ad4.z : ad4.w;

    // pass 2: fused exp, denom and weighted feature sum (lane owns 8 cols)
    float denom = 0.f;
    float4 accA = make_float4(0.f, 0.f, 0.f, 0.f);
    float4 accB = make_float4(0.f, 0.f, 0.f, 0.f);
    int colbase = lane * 8;
    for (int i = start; i < end; i++) {
        int s = g_csrsrc[i];
        float a = lrelu(g_asrc1[s * 4 + head] + ad);
        float w = expf(a - mh);
        denom += w;
        const float* hp = g_h1 + (size_t)s * H1C1 + colbase;
        float4 v0 = *(const float4*)hp;
        float4 v1 = *(const float4*)(hp + 4);
        accA.x += w * v0.x; accA.y += w * v0.y; accA.z += w * v0.z; accA.w += w * v0.w;
        accB.x += w * v1.x; accB.y += w * v1.y; accB.z += w * v1.z; accB.w += w * v1.w;
    }
    float inv = 1.f / (denom + 1e-16f);
    const float* bb = b1 + colbase;
    float4 o0, o1;
    o0.x = elu(accA.x * inv + bb[0]); o0.y = elu(accA.y * inv + bb[1]);
    o0.z = elu(accA.z * inv + bb[2]); o0.w = elu(accA.w * inv + bb[3]);
    o1.x = elu(accB.x * inv + bb[4]); o1.y = elu(accB.y * inv + bb[5]);
    o1.z = elu(accB.z * inv + bb[6]); o1.w = elu(accB.w * inv + bb[7]);
    float* op = g_out1 + (size_t)warp * H1C1 + colbase;
    *(float4*)op = o0;
    *(float4*)(op + 4) = o1;
}

// ---------------- layer-2 aggregation: warp per dst node, 1 head ----------
__global__ void aggregate2(const float* __restrict__ b2) {
    int warp = (blockIdx.x * blockDim.x + threadIdx.x) >> 5;
    if (warp >= NN) return;
    int lane = threadIdx.x & 31;
    int start = g_rowptr[warp], end = g_rowptr[warp + 1];
    float ad = g_adst2[warp];

    float m = -1e30f;
    for (int i = start + lane; i < end; i += 32) {
        int s = g_csrsrc[i];
        m = fmaxf(m, lrelu(g_asrc2[s] + ad));
    }
#pragma unroll
    for (int off = 16; off; off >>= 1)
        m = fmaxf(m, __shfl_xor_sync(0xffffffffu, m, off));

    float denom = 0.f;
    float4 acc = make_float4(0.f, 0.f, 0.f, 0.f);
    int colbase = lane * 4;
    for (int i = start; i < end; i++) {
        int s = g_csrsrc[i];
        float a = lrelu(g_asrc2[s] + ad);
        float w = expf(a - m);
        denom += w;
        float4 v = *(const float4*)(g_h2 + (size_t)s * C2 + colbase);
        acc.x += w * v.x; acc.y += w * v.y; acc.z += w * v.z; acc.w += w * v.w;
    }
    float inv = 1.f / (denom + 1e-16f);
    const float* bb = b2 + colbase;
    float4 o;
    o.x = elu(acc.x * inv + bb[0]);
    o.y = elu(acc.y * inv + bb[1]);
    o.z = elu(acc.z * inv + bb[2]);
    o.w = elu(acc.w * inv + bb[3]);
    *(float4*)(g_out2 + (size_t)warp * C2 + colbase) = o;
}

// ---------------- pooling ---------------------------------------------------
__global__ void counts_kernel(const void* __restrict__ batch) {
    int n = blockIdx.x * blockDim.x + threadIdx.x;
    if (n < NN) atomicAdd(&g_counts[ld_idx(batch, n, g_is64)], 1);
}

__global__ void pool_kernel(const void* __restrict__ batch) {
    const int NPB = 200;
    int c = threadIdx.x;               // 128 threads = feature dim
    int is64 = g_is64;
    int base = blockIdx.x * NPB;
    int lim = base + NPB < NN ? base + NPB : NN;
    int cur = -1;
    float acc = 0.f;
    for (int n = base; n < lim; n++) {
        int g = ld_idx(batch, n, is64);
        if (g != cur) {
            if (cur >= 0) atomicAdd(&g_pool[cur * C2 + c], acc);
            cur = g; acc = 0.f;
        }
        acc += g_out2[(size_t)n * C2 + c];
    }
    if (cur >= 0) atomicAdd(&g_pool[cur * C2 + c], acc);
}

__global__ void final_kernel(const float* __restrict__ lin_w, const float* __restrict__ lin_b,
                             float* __restrict__ out) {
    int t = threadIdx.x;
    if (t >= NG * NCLS) return;
    int g = t / NCLS, cls = t % NCLS;
    float cnt = fmaxf((float)g_counts[g], 1.f);
    float s = 0.f;
    for (int c = 0; c < C2; c++) s += g_pool[g * C2 + c] * lin_w[c * NCLS + cls];
    out[t] = s / cnt + lin_b[cls];
}

// ---------------- launch ----------------------------------------------------
extern "C" void kernel_launch(void* const* d_in, const int* in_sizes, int n_in,
                              void* d_out, int out_size) {
    const float* x        = (const float*)d_in[0];
    const void*  ei       = d_in[1];               // int32 or int64, detected on device
    const void*  bat      = d_in[2];
    const float* W1       = (const float*)d_in[3];
    const float* att_src1 = (const float*)d_in[4];
    const float* att_dst1 = (const float*)d_in[5];
    const float* b1       = (const float*)d_in[6];
    const float* W2       = (const float*)d_in[7];
    const float* att_src2 = (const float*)d_in[8];
    const float* att_dst2 = (const float*)d_in[9];
    const float* b2       = (const float*)d_in[10];
    const float* lin_w    = (const float*)d_in[11];
    const float* lin_b    = (const float*)d_in[12];
    float* out            = (float*)d_out;

    float* h1p;   cudaGetSymbolAddress((void**)&h1p, g_h1);
    float* out1p; cudaGetSymbolAddress((void**)&out1p, g_out1);
    float* h2p;   cudaGetSymbolAddress((void**)&h2p, g_h2);

    // init + dtype detection
    detect_kernel<<<1, 32>>>((const unsigned int*)ei);
    zero_kernel<<<(NN + 255) / 256, 256>>>();

    // CSR build (graph is same for both layers)
    degree_kernel<<<(ET + 255) / 256, 256>>>(ei);
    scan_kernel<<<1, 1024>>>();
    scatter_kernel<<<(ET + 255) / 256, 256>>>(ei);

    // layer 1
    {
        dim3 grid((NN + 63) / 64, H1C1 / 64);
        sgemm64<<<grid, 256>>>(x, W1, h1p, NN, H1C1, FIN);
    }
    attn_coef1<<<(NN * 32 + 255) / 256, 256>>>(att_src1, att_dst1);
    aggregate1<<<(NN * 32 + 255) / 256, 256>>>(b1);

    // layer 2
    {
        dim3 grid((NN + 63) / 64, C2 / 64);
        sgemm64<<<grid, 256>>>(out1p, W2, h2p, NN, C2, H1C1);
    }
    attn_coef2<<<(NN * 32 + 255) / 256, 256>>>(att_src2, att_dst2);
    aggregate2<<<(NN * 32 + 255) / 256, 256>>>(b2);

    // pool + classify
    counts_kernel<<<(NN + 255) / 256, 256>>>(bat);
    pool_kernel<<<(NN + 199) / 200, C2>>>(bat);
    final_kernel<<<1, 256>>>(lin_w, lin_b, out);
}

// round 5
// speedup vs baseline: 1.1763x; 1.1763x over previous
#include <cuda_runtime.h>
#include <math.h>

// Problem dims
#define NN 50000
#define EE 800000
#define ET 850000      // EE + NN self-loops
#define FIN 128
#define H1C1 256       // 4 heads * 64
#define C2 128
#define NG 32
#define NCLS 5
#define NEG_SLOPE 0.2f

#define SCAN_B 512
#define SCAN_G ((NN + SCAN_B - 1) / SCAN_B)   // 98

// ---------------- scratch (device globals; no allocations allowed) --------
__device__ float g_h1[(size_t)NN * H1C1];     // x @ W1
__device__ float g_out1[(size_t)NN * H1C1];   // elu(gat1)
__device__ float g_h2[(size_t)NN * C2];       // out1 @ W2
__device__ float g_out2[(size_t)NN * C2];     // elu(gat2)
__device__ float g_asrc1[NN * 4], g_adst1[NN * 4];
__device__ float g_asrc2[NN], g_adst2[NN];
__device__ int   g_deg[NN];
__device__ int   g_rowptr[NN + 1];
__device__ int   g_cursor[NN];
__device__ int   g_csrsrc[ET];
__device__ int   g_part[SCAN_G];
__device__ float g_pool[NG * C2];
__device__ int   g_counts[NG];
__device__ int   g_is64;                      // index dtype flag (1 = int64, 0 = int32)

// ---------------- utility -------------------------------------------------
__device__ __forceinline__ float lrelu(float x) { return x > 0.f ? x : NEG_SLOPE * x; }
__device__ __forceinline__ float elu(float x)   { return x > 0.f ? x : (expf(x) - 1.f); }

__device__ __forceinline__ int ld_idx(const void* p, long long i, int is64) {
    if (is64) return (int)((const long long*)p)[i];
    return ((const int*)p)[i];
}

// ---------------- dtype detection ------------------------------------------
__global__ void detect_kernel(const unsigned int* __restrict__ w) {
    if (threadIdx.x == 0) {
        unsigned int nz = 0;
        for (int i = 0; i < 128; i++) nz |= w[2 * i + 1];
        g_is64 = (nz == 0u) ? 1 : 0;
    }
}

// ---------------- zero init -----------------------------------------------
__global__ void zero_kernel() {
    int i = blockIdx.x * blockDim.x + threadIdx.x;
    if (i < NN) g_deg[i] = 0;
    if (i < NG * C2) g_pool[i] = 0.f;
    if (i < NG) g_counts[i] = 0;
}

// ---------------- SGEMM: C[M,Nn] = A[M,K] * B[K,Nn] ------------------------
// 128x64 block tile, BK=16, 256 threads, 8x4 per-thread register tile.
// Nn and K must be multiples of 64/16 (true here); only M edge is guarded.
__global__ void sgemm128(const float* __restrict__ A, const float* __restrict__ B,
                         float* __restrict__ C, int M, int Nn, int K) {
    __shared__ __align__(16) float As[16][128];
    __shared__ __align__(16) float Bs[16][64];
    int tid = threadIdx.x;
    int tx = tid & 15, ty = tid >> 4;
    int m0 = blockIdx.x * 128, n0 = blockIdx.y * 64;

    float acc[8][4];
#pragma unroll
    for (int i = 0; i < 8; i++)
#pragma unroll
        for (int j = 0; j < 4; j++) acc[i][j] = 0.f;

    int brow = tid >> 4;            // 0..15
    int bcol = (tid & 15) * 4;

    for (int kt = 0; kt < K; kt += 16) {
        // load A tile (128 rows x 16 cols) transposed into As[k][m]
#pragma unroll
        for (int u = 0; u < 2; u++) {
            int slot = tid * 2 + u;           // 0..511
            int row = slot >> 2;              // 0..127
            int col = (slot & 3) * 4;         // 0,4,8,12
            float4 av = (m0 + row < M)
                ? *(const float4*)(A + (size_t)(m0 + row) * K + kt + col)
                : make_float4(0.f, 0.f, 0.f, 0.f);
            As[col + 0][row] = av.x;
            As[col + 1][row] = av.y;
            As[col + 2][row] = av.z;
            As[col + 3][row] = av.w;
        }
        *(float4*)&Bs[brow][bcol] = *(const float4*)(B + (size_t)(kt + brow) * Nn + n0 + bcol);
        __syncthreads();
#pragma unroll
        for (int k = 0; k < 16; k++) {
            float4 a0 = *(float4*)&As[k][ty * 8];
            float4 a1 = *(float4*)&As[k][ty * 8 + 4];
            float4 b  = *(float4*)&Bs[k][tx * 4];
            acc[0][0] += a0.x * b.x; acc[0][1] += a0.x * b.y; acc[0][2] += a0.x * b.z; acc[0][3] += a0.x * b.w;
            acc[1][0] += a0.y * b.x; acc[1][1] += a0.y * b.y; acc[1][2] += a0.y * b.z; acc[1][3] += a0.y * b.w;
            acc[2][0] += a0.z * b.x; acc[2][1] += a0.z * b.y; acc[2][2] += a0.z * b.z; acc[2][3] += a0.z * b.w;
            acc[3][0] += a0.w * b.x; acc[3][1] += a0.w * b.y; acc[3][2] += a0.w * b.z; acc[3][3] += a0.w * b.w;
            acc[4][0] += a1.x * b.x; acc[4][1] += a1.x * b.y; acc[4][2] += a1.x * b.z; acc[4][3] += a1.x * b.w;
            acc[5][0] += a1.y * b.x; acc[5][1] += a1.y * b.y; acc[5][2] += a1.y * b.z; acc[5][3] += a1.y * b.w;
            acc[6][0] += a1.z * b.x; acc[6][1] += a1.z * b.y; acc[6][2] += a1.z * b.z; acc[6][3] += a1.z * b.w;
            acc[7][0] += a1.w * b.x; acc[7][1] += a1.w * b.y; acc[7][2] += a1.w * b.z; acc[7][3] += a1.w * b.w;
        }
        __syncthreads();
    }
#pragma unroll
    for (int i = 0; i < 8; i++) {
        int r = m0 + ty * 8 + i;
        if (r < M) {
            float4 o = make_float4(acc[i][0], acc[i][1], acc[i][2], acc[i][3]);
            *(float4*)(C + (size_t)r * Nn + n0 + tx * 4) = o;
        }
    }
}

// ---------------- attention coefficients (layer 1, 4 heads x 64) ----------
__global__ void attn_coef1(const float* __restrict__ att_src, const float* __restrict__ att_dst) {
    int warp = (blockIdx.x * blockDim.x + threadIdx.x) >> 5;
    if (warp >= NN) return;
    int lane = threadIdx.x & 31;
    int head = lane >> 3;
    int lc = (lane & 7) * 8;
    const float* hrow = g_h1 + (size_t)warp * H1C1 + head * 64 + lc;
    float4 h0 = *(const float4*)hrow;
    float4 h1v = *(const float4*)(hrow + 4);
    const float* as_ = att_src + head * 64 + lc;
    const float* ad_ = att_dst + head * 64 + lc;
    float s = h0.x * as_[0] + h0.y * as_[1] + h0.z * as_[2] + h0.w * as_[3]
            + h1v.x * as_[4] + h1v.y * as_[5] + h1v.z * as_[6] + h1v.w * as_[7];
    float d = h0.x * ad_[0] + h0.y * ad_[1] + h0.z * ad_[2] + h0.w * ad_[3]
            + h1v.x * ad_[4] + h1v.y * ad_[5] + h1v.z * ad_[6] + h1v.w * ad_[7];
#pragma unroll
    for (int off = 4; off; off >>= 1) {
        s += __shfl_xor_sync(0xffffffffu, s, off);
        d += __shfl_xor_sync(0xffffffffu, d, off);
    }
    if ((lane & 7) == 0) {
        g_asrc1[warp * 4 + head] = s;
        g_adst1[warp * 4 + head] = d;
    }
}

// ---------------- attention coefficients (layer 2, 1 head x 128) ----------
__global__ void attn_coef2(const float* __restrict__ att_src, const float* __restrict__ att_dst) {
    int warp = (blockIdx.x * blockDim.x + threadIdx.x) >> 5;
    if (warp >= NN) return;
    int lane = threadIdx.x & 31;
    const float* hrow = g_h2 + (size_t)warp * C2 + lane * 4;
    float4 h = *(const float4*)hrow;
    const float* as_ = att_src + lane * 4;
    const float* ad_ = att_dst + lane * 4;
    float s = h.x * as_[0] + h.y * as_[1] + h.z * as_[2] + h.w * as_[3];
    float d = h.x * ad_[0] + h.y * ad_[1] + h.z * ad_[2] + h.w * ad_[3];
#pragma unroll
    for (int off = 16; off; off >>= 1) {
        s += __shfl_xor_sync(0xffffffffu, s, off);
        d += __shfl_xor_sync(0xffffffffu, d, off);
    }
    if (lane == 0) { g_asrc2[warp] = s; g_adst2[warp] = d; }
}

// ---------------- CSR build -------------------------------------------------
__global__ void degree_kernel(const void* __restrict__ ei) {
    int e = blockIdx.x * blockDim.x + threadIdx.x;
    if (e >= ET) return;
    int is64 = g_is64;
    int d = (e < EE) ? ld_idx(ei, (long long)EE + e, is64) : (e - EE);
    atomicAdd(&g_deg[d], 1);
}

// ---------- 3-phase parallel exclusive scan over g_deg ----------------------
__global__ void scan_phase1() {
    __shared__ int sh[SCAN_B];
    int t = threadIdx.x;
    int i = blockIdx.x * SCAN_B + t;
    sh[t] = (i < NN) ? g_deg[i] : 0;
    __syncthreads();
#pragma unroll
    for (int off = SCAN_B / 2; off; off >>= 1) {
        if (t < off) sh[t] += sh[t + off];
        __syncthreads();
    }
    if (t == 0) g_part[blockIdx.x] = sh[0];
}

__global__ void scan_phase2() {   // 1 block, 128 threads: scan 98 partials
    __shared__ int sh[128];
    int t = threadIdx.x;
    int v = (t < SCAN_G) ? g_part[t] : 0;
    sh[t] = v;
    __syncthreads();
#pragma unroll
    for (int off = 1; off < 128; off <<= 1) {
        int u = (t >= off) ? sh[t - off] : 0;
        __syncthreads();
        sh[t] += u;
        __syncthreads();
    }
    if (t < SCAN_G) g_part[t] = sh[t] - v;   // exclusive
    if (t == 127) g_rowptr[NN] = sh[127];
}

__global__ void scan_phase3() {
    __shared__ int sh[SCAN_B];
    int t = threadIdx.x;
    int i = blockIdx.x * SCAN_B + t;
    int v = (i < NN) ? g_deg[i] : 0;
    sh[t] = v;
    __syncthreads();
#pragma unroll
    for (int off = 1; off < SCAN_B; off <<= 1) {
        int u = (t >= off) ? sh[t - off] : 0;
        __syncthreads();
        sh[t] += u;
        __syncthreads();
    }
    if (i < NN) {
        int ex = g_part[blockIdx.x] + sh[t] - v;
        g_rowptr[i] = ex;
        g_cursor[i] = ex;
    }
}

__global__ void scatter_kernel(const void* __restrict__ ei) {
    int e = blockIdx.x * blockDim.x + threadIdx.x;
    if (e >= ET) return;
    int is64 = g_is64;
    int s, d;
    if (e < EE) { s = ld_idx(ei, e, is64); d = ld_idx(ei, (long long)EE + e, is64); }
    else        { s = e - EE;              d = e - EE; }
    int pos = atomicAdd(&g_cursor[d], 1);
    g_csrsrc[pos] = s;
}

// ---------------- layer-1 aggregation: warp per dst node ------------------
__global__ void aggregate1(const float* __restrict__ b1) {
    int warp = (blockIdx.x * blockDim.x + threadIdx.x) >> 5;
    if (warp >= NN) return;
    int lane = threadIdx.x & 31;
    int head = lane >> 3;
    int start = g_rowptr[warp], end = g_rowptr[warp + 1];
    float4 ad4 = *(const float4*)(g_adst1 + warp * 4);

    // pass 1: per-head max over incoming edges
    float m0 = -1e30f, m1 = -1e30f, m2 = -1e30f, m3 = -1e30f;
    for (int i = start + lane; i < end; i += 32) {
        int s = g_csrsrc[i];
        float4 as4 = *(const float4*)(g_asrc1 + s * 4);
        m0 = fmaxf(m0, lrelu(as4.x + ad4.x));
        m1 = fmaxf(m1, lrelu(as4.y + ad4.y));
        m2 = fmaxf(m2, lrelu(as4.z + ad4.z));
        m3 = fmaxf(m3, lrelu(as4.w + ad4.w));
    }
#pragma unroll
    for (int off = 16; off; off >>= 1) {
        m0 = fmaxf(m0, __shfl_xor_sync(0xffffffffu, m0, off));
        m1 = fmaxf(m1, __shfl_xor_sync(0xffffffffu, m1, off));
        m2 = fmaxf(m2, __shfl_xor_sync(0xffffffffu, m2, off));
        m3 = fmaxf(m3, __shfl_xor_sync(0xffffffffu, m3, off));
    }
    float mh = (head == 0) ? m0 : (head == 1) ? m1 : (head == 2) ? m2 : m3;
    float ad = (head == 0) ? ad4.x : (head == 1) ? ad4.y : (head == 2) ? ad4.z : ad4.w;

    // pass 2: fused exp, denom and weighted feature sum; 2-way unrolled for MLP
    float denom = 0.f;
    float4 accA = make_float4(0.f, 0.f, 0.f, 0.f);
    float4 accB = make_float4(0.f, 0.f, 0.f, 0.f);
    int colbase = lane * 8;
    int i = start;
    for (; i + 1 < end; i += 2) {
        int s0 = g_csrsrc[i], s1 = g_csrsrc[i + 1];
        float a0 = lrelu(g_asrc1[s0 * 4 + head] + ad);
        float a1 = lrelu(g_asrc1[s1 * 4 + head] + ad);
        const float* hp0 = g_h1 + (size_t)s0 * H1C1 + colbase;
        const float* hp1 = g_h1 + (size_t)s1 * H1C1 + colbase;
        float4 u0 = *(const float4*)hp0;
        float4 u1 = *(const float4*)(hp0 + 4);
        float4 v0 = *(const float4*)hp1;
        float4 v1 = *(const float4*)(hp1 + 4);
        float w0 = expf(a0 - mh), w1 = expf(a1 - mh);
        denom += w0 + w1;
        accA.x += w0 * u0.x + w1 * v0.x; accA.y += w0 * u0.y + w1 * v0.y;
        accA.z += w0 * u0.z + w1 * v0.z; accA.w += w0 * u0.w + w1 * v0.w;
        accB.x += w0 * u1.x + w1 * v1.x; accB.y += w0 * u1.y + w1 * v1.y;
        accB.z += w0 * u1.z + w1 * v1.z; accB.w += w0 * u1.w + w1 * v1.w;
    }
    if (i < end) {
        int s0 = g_csrsrc[i];
        float a0 = lrelu(g_asrc1[s0 * 4 + head] + ad);
        float w0 = expf(a0 - mh);
        denom += w0;
        const float* hp0 = g_h1 + (size_t)s0 * H1C1 + colbase;
        float4 u0 = *(const float4*)hp0;
        float4 u1 = *(const float4*)(hp0 + 4);
        accA.x += w0 * u0.x; accA.y += w0 * u0.y; accA.z += w0 * u0.z; accA.w += w0 * u0.w;
        accB.x += w0 * u1.x; accB.y += w0 * u1.y; accB.z += w0 * u1.z; accB.w += w0 * u1.w;
    }
    float inv = 1.f / (denom + 1e-16f);
    const float* bb = b1 + colbase;
    float4 o0, o1;
    o0.x = elu(accA.x * inv + bb[0]); o0.y = elu(accA.y * inv + bb[1]);
    o0.z = elu(accA.z * inv + bb[2]); o0.w = elu(accA.w * inv + bb[3]);
    o1.x = elu(accB.x * inv + bb[4]); o1.y = elu(accB.y * inv + bb[5]);
    o1.z = elu(accB.z * inv + bb[6]); o1.w = elu(accB.w * inv + bb[7]);
    float* op = g_out1 + (size_t)warp * H1C1 + colbase;
    *(float4*)op = o0;
    *(float4*)(op + 4) = o1;
}

// ---------------- layer-2 aggregation: warp per dst node, 1 head ----------
__global__ void aggregate2(const float* __restrict__ b2) {
    int warp = (blockIdx.x * blockDim.x + threadIdx.x) >> 5;
    if (warp >= NN) return;
    int lane = threadIdx.x & 31;
    int start = g_rowptr[warp], end = g_rowptr[warp + 1];
    float ad = g_adst2[warp];

    float m = -1e30f;
    for (int i = start + lane; i < end; i += 32) {
        int s = g_csrsrc[i];
        m = fmaxf(m, lrelu(g_asrc2[s] + ad));
    }
#pragma unroll
    for (int off = 16; off; off >>= 1)
        m = fmaxf(m, __shfl_xor_sync(0xffffffffu, m, off));

    float denom = 0.f;
    float4 acc = make_float4(0.f, 0.f, 0.f, 0.f);
    int colbase = lane * 4;
    int i = start;
    for (; i + 1 < end; i += 2) {
        int s0 = g_csrsrc[i], s1 = g_csrsrc[i + 1];
        float a0 = lrelu(g_asrc2[s0] + ad);
        float a1 = lrelu(g_asrc2[s1] + ad);
        float4 u = *(const float4*)(g_h2 + (size_t)s0 * C2 + colbase);
        float4 v = *(const float4*)(g_h2 + (size_t)s1 * C2 + colbase);
        float w0 = expf(a0 - m), w1 = expf(a1 - m);
        denom += w0 + w1;
        acc.x += w0 * u.x + w1 * v.x; acc.y += w0 * u.y + w1 * v.y;
        acc.z += w0 * u.z + w1 * v.z; acc.w += w0 * u.w + w1 * v.w;
    }
    if (i < end) {
        int s0 = g_csrsrc[i];
        float a0 = lrelu(g_asrc2[s0] + ad);
        float w0 = expf(a0 - m);
        denom += w0;
        float4 u = *(const float4*)(g_h2 + (size_t)s0 * C2 + colbase);
        acc.x += w0 * u.x; acc.y += w0 * u.y; acc.z += w0 * u.z; acc.w += w0 * u.w;
    }
    float inv = 1.f / (denom + 1e-16f);
    const float* bb = b2 + colbase;
    float4 o;
    o.x = elu(acc.x * inv + bb[0]);
    o.y = elu(acc.y * inv + bb[1]);
    o.z = elu(acc.z * inv + bb[2]);
    o.w = elu(acc.w * inv + bb[3]);
    *(float4*)(g_out2 + (size_t)warp * C2 + colbase) = o;
}

// ---------------- pooling ---------------------------------------------------
__global__ void counts_kernel(const void* __restrict__ batch) {
    int n = blockIdx.x * blockDim.x + threadIdx.x;
    if (n < NN) atomicAdd(&g_counts[ld_idx(batch, n, g_is64)], 1);
}

__global__ void pool_kernel(const void* __restrict__ batch) {
    const int NPB = 200;
    int c = threadIdx.x;               // 128 threads = feature dim
    int is64 = g_is64;
    int base = blockIdx.x * NPB;
    int lim = base + NPB < NN ? base + NPB : NN;
    int cur = -1;
    float acc = 0.f;
    for (int n = base; n < lim; n++) {
        int g = ld_idx(batch, n, is64);
        if (g != cur) {
            if (cur >= 0) atomicAdd(&g_pool[cur * C2 + c], acc);
            cur = g; acc = 0.f;
        }
        acc += g_out2[(size_t)n * C2 + c];
    }
    if (cur >= 0) atomicAdd(&g_pool[cur * C2 + c], acc);
}

__global__ void final_kernel(const float* __restrict__ lin_w, const float* __restrict__ lin_b,
                             float* __restrict__ out) {
    int t = threadIdx.x;
    if (t >= NG * NCLS) return;
    int g = t / NCLS, cls = t % NCLS;
    float cnt = fmaxf((float)g_counts[g], 1.f);
    float s = 0.f;
    for (int c = 0; c < C2; c++) s += g_pool[g * C2 + c] * lin_w[c * NCLS + cls];
    out[t] = s / cnt + lin_b[cls];
}

// ---------------- launch ----------------------------------------------------
extern "C" void kernel_launch(void* const* d_in, const int* in_sizes, int n_in,
                              void* d_out, int out_size) {
    const float* x        = (const float*)d_in[0];
    const void*  ei       = d_in[1];               // int32 or int64, detected on device
    const void*  bat      = d_in[2];
    const float* W1       = (const float*)d_in[3];
    const float* att_src1 = (const float*)d_in[4];
    const float* att_dst1 = (const float*)d_in[5];
    const float* b1       = (const float*)d_in[6];
    const float* W2       = (const float*)d_in[7];
    const float* att_src2 = (const float*)d_in[8];
    const float* att_dst2 = (const float*)d_in[9];
    const float* b2       = (const float*)d_in[10];
    const float* lin_w    = (const float*)d_in[11];
    const float* lin_b    = (const float*)d_in[12];
    float* out            = (float*)d_out;

    float* h1p;   cudaGetSymbolAddress((void**)&h1p, g_h1);
    float* out1p; cudaGetSymbolAddress((void**)&out1p, g_out1);
    float* h2p;   cudaGetSymbolAddress((void**)&h2p, g_h2);

    // init + dtype detection
    detect_kernel<<<1, 32>>>((const unsigned int*)ei);
    zero_kernel<<<(NN + 255) / 256, 256>>>();

    // CSR build (graph is same for both layers)
    degree_kernel<<<(ET + 255) / 256, 256>>>(ei);
    scan_phase1<<<SCAN_G, SCAN_B>>>();
    scan_phase2<<<1, 128>>>();
    scan_phase3<<<SCAN_G, SCAN_B>>>();
    scatter_kernel<<<(ET + 255) / 256, 256>>>(ei);

    // layer 1
    {
        dim3 grid((NN + 127) / 128, H1C1 / 64);
        sgemm128<<<grid, 256>>>(x, W1, h1p, NN, H1C1, FIN);
    }
    attn_coef1<<<(NN * 32 + 255) / 256, 256>>>(att_src1, att_dst1);
    aggregate1<<<(NN * 32 + 255) / 256, 256>>>(b1);

    // layer 2
    {
        dim3 grid((NN + 127) / 128, C2 / 64);
        sgemm128<<<grid, 256>>>(out1p, W2, h2p, NN, C2, H1C1);
    }
    attn_coef2<<<(NN * 32 + 255) / 256, 256>>>(att_src2, att_dst2);
    aggregate2<<<(NN * 32 + 255) / 256, 256>>>(b2);

    // pool + classify
    counts_kernel<<<(NN + 255) / 256, 256>>>(bat);
    pool_kernel<<<(NN + 199) / 200, C2>>>(bat);
    final_kernel<<<1, 256>>>(lin_w, lin_b, out);
}

// round 7
// speedup vs baseline: 1.7098x; 1.4535x over previous
#include <cuda_runtime.h>
#include <cuda_fp16.h>
#include <mma.h>
#include <math.h>

using namespace nvcuda;

// Problem dims
#define NN 50000
#define EE 800000
#define ET 850000      // EE + NN self-loops
#define FIN 128
#define H1C1 256       // 4 heads * 64
#define C2 128
#define NG 32
#define NCLS 5
#define NEG_SLOPE 0.2f

#define SCAN_B 512
#define SCAN_G ((NN + SCAN_B - 1) / SCAN_B)   // 98

// ---------------- scratch (device globals; no allocations allowed) --------
__device__ __half g_xh[(size_t)NN * FIN];      // x in fp16
__device__ __half g_w1h[FIN * H1C1];           // W1 fp16
__device__ __half g_w2h[H1C1 * C2];            // W2 fp16
__device__ __half g_h1h[(size_t)NN * H1C1];    // x @ W1  (fp16)
__device__ __half g_out1h[(size_t)NN * H1C1];  // elu(gat1) (fp16, GEMM2 input)
__device__ __half g_h2h[(size_t)NN * C2];      // out1 @ W2 (fp16)
__device__ float  g_out2[(size_t)NN * C2];     // elu(gat2) (fp32 for pooling)
__device__ float  g_asrc1[NN * 4], g_adst1[NN * 4];
__device__ float  g_asrc2[NN], g_adst2[NN];
__device__ int    g_deg[NN];
__device__ int    g_rowptr[NN + 1];
__device__ int    g_cursor[NN];
__device__ int    g_csrsrc[ET];
__device__ int    g_part[SCAN_G];
__device__ float  g_pool[NG * C2];
__device__ int    g_counts[NG];
__device__ int    g_is64;

// ---------------- utility -------------------------------------------------
__device__ __forceinline__ float lrelu(float x) { return x > 0.f ? x : NEG_SLOPE * x; }
__device__ __forceinline__ float elu(float x)   { return x > 0.f ? x : (expf(x) - 1.f); }

__device__ __forceinline__ int ld_idx(const void* p, long long i, int is64) {
    if (is64) return (int)((const long long*)p)[i];
    return ((const int*)p)[i];
}

// ---------------- dtype detection ------------------------------------------
__global__ void detect_kernel(const unsigned int* __restrict__ w) {
    if (threadIdx.x == 0) {
        unsigned int nz = 0;
        for (int i = 0; i < 128; i++) nz |= w[2 * i + 1];
        g_is64 = (nz == 0u) ? 1 : 0;
    }
}

// ---------------- zero init -----------------------------------------------
__global__ void zero_kernel() {
    int i = blockIdx.x * blockDim.x + threadIdx.x;
    if (i < NN) g_deg[i] = 0;
    if (i < NG * C2) g_pool[i] = 0.f;
    if (i < NG) g_counts[i] = 0;
}

// ---------------- fp32 -> fp16 convert (n multiple of 4) -------------------
__global__ void f2h_kernel(const float* __restrict__ src, __half* __restrict__ dst, int n) {
    int i = (blockIdx.x * blockDim.x + threadIdx.x) * 4;
    if (i >= n) return;
    float4 v = *(const float4*)(src + i);
    __half h[4] = { __float2half(v.x), __float2half(v.y), __float2half(v.z), __float2half(v.w) };
    *(unsigned long long*)(dst + i) = *(unsigned long long*)h;
}

// ---------------- fp16 WMMA GEMM: C[M,Nn] = A[M,K] * B[K,Nn] ---------------
// Block tile 128x128, BK=32, 256 threads (8 warps: 4 M-warps x 2 N-warps),
// warp tile 32x64 (2x4 wmma 16x16x16 fragments), fp32 accumulate.
// Nn, K multiples of 32; only M edge guarded. C written as fp16.
#define ASTRIDE 40
#define BSTRIDE 136
#define CSTRIDE 72
__global__ __launch_bounds__(256) void hgemm128(const __half* __restrict__ A,
                                                const __half* __restrict__ B,
                                                __half* __restrict__ C,
                                                int M, int Nn, int K) {
    __shared__ __align__(16) unsigned char smem_raw[128 * CSTRIDE * 4]; // 36.9KB (>= mainloop 18.9KB)
    __half* As = (__half*)smem_raw;            // 128 x ASTRIDE
    __half* Bs = As + 128 * ASTRIDE;           // 32 x BSTRIDE
    float*  St = (float*)smem_raw;             // epilogue staging 128 x CSTRIDE

    int tid = threadIdx.x;
    int wid = tid >> 5;
    int warp_m = wid & 3;         // 0..3
    int warp_n = wid >> 2;        // 0..1
    int m0 = blockIdx.x * 128, n0 = blockIdx.y * 128;

    wmma::fragment<wmma::accumulator, 16, 16, 16, float> acc[2][4];
#pragma unroll
    for (int i = 0; i < 2; i++)
#pragma unroll
        for (int j = 0; j < 4; j++) wmma::fill_fragment(acc[i][j], 0.f);

    for (int kt = 0; kt < K; kt += 32) {
        // load A tile: 128 rows x 32 halves; 512 chunks of 8 halves (16B)
#pragma unroll
        for (int u = 0; u < 2; u++) {
            int chunk = tid * 2 + u;
            int row = chunk >> 2;
            int c8 = (chunk & 3) * 8;
            int4 v = make_int4(0, 0, 0, 0);
            if (m0 + row < M) v = *(const int4*)(A + (size_t)(m0 + row) * K + kt + c8);
            *(int4*)(As + row * ASTRIDE + c8) = v;
        }
        // load B tile: 32 rows x 128 halves
#pragma unroll
        for (int u = 0; u < 2; u++) {
            int chunk = tid * 2 + u;
            int row = chunk >> 4;
            int c8 = (chunk & 15) * 8;
            *(int4*)(Bs + row * BSTRIDE + c8) = *(const int4*)(B + (size_t)(kt + row) * Nn + n0 + c8);
        }
        __syncthreads();
#pragma unroll
        for (int kk = 0; kk < 2; kk++) {
            wmma::fragment<wmma::matrix_a, 16, 16, 16, __half, wmma::row_major> af[2];
            wmma::fragment<wmma::matrix_b, 16, 16, 16, __half, wmma::row_major> bf[4];
#pragma unroll
            for (int i = 0; i < 2; i++)
                wmma::load_matrix_sync(af[i], As + (warp_m * 32 + i * 16) * ASTRIDE + kk * 16, ASTRIDE);
#pragma unroll
            for (int j = 0; j < 4; j++)
                wmma::load_matrix_sync(bf[j], Bs + (kk * 16) * BSTRIDE + warp_n * 64 + j * 16, BSTRIDE);
#pragma unroll
            for (int i = 0; i < 2; i++)
#pragma unroll
                for (int j = 0; j < 4; j++)
                    wmma::mma_sync(acc[i][j], af[i], bf[j], acc[i][j]);
        }
        __syncthreads();
    }

    // epilogue: stage fp32 frags to smem per N-half, convert + store fp16
#pragma unroll
    for (int p = 0; p < 2; p++) {
        __syncthreads();
        if (warp_n == p) {
#pragma unroll
            for (int i = 0; i < 2; i++)
#pragma unroll
                for (int j = 0; j < 4; j++)
                    wmma::store_matrix_sync(St + (warp_m * 32 + i * 16) * CSTRIDE + j * 16,
                                            acc[i][j], CSTRIDE, wmma::mem_row_major);
        }
        __syncthreads();
#pragma unroll
        for (int r = 0; r < 4; r++) {
            int row = (tid >> 3) * 4 + r;        // 0..127
            int col = (tid & 7) * 8;             // 0..56
            if (m0 + row < M) {
                const float* sp = St + row * CSTRIDE + col;
                __half h[8];
#pragma unroll
                for (int q = 0; q < 8; q++) h[q] = __float2half(sp[q]);
                *(int4*)(C + (size_t)(m0 + row) * Nn + n0 + p * 64 + col) = *(int4*)h;
            }
        }
    }
}

// ---------------- attention coefficients (layer 1, 4 heads x 64) ----------
__global__ void attn_coef1(const float* __restrict__ att_src, const float* __restrict__ att_dst) {
    int warp = (blockIdx.x * blockDim.x + threadIdx.x) >> 5;
    if (warp >= NN) return;
    int lane = threadIdx.x & 31;
    int head = lane >> 3;
    int lc = (lane & 7) * 8;
    const __half* hrow = g_h1h + (size_t)warp * H1C1 + head * 64 + lc;
    __half2 hv[4];
    *(int4*)hv = *(const int4*)hrow;
    const float* as_ = att_src + head * 64 + lc;
    const float* ad_ = att_dst + head * 64 + lc;
    float s = 0.f, d = 0.f;
#pragma unroll
    for (int k = 0; k < 4; k++) {
        float2 f = __half22float2(hv[k]);
        s += f.x * as_[2 * k] + f.y * as_[2 * k + 1];
        d += f.x * ad_[2 * k] + f.y * ad_[2 * k + 1];
    }
#pragma unroll
    for (int off = 4; off; off >>= 1) {
        s += __shfl_xor_sync(0xffffffffu, s, off);
        d += __shfl_xor_sync(0xffffffffu, d, off);
    }
    if ((lane & 7) == 0) {
        g_asrc1[warp * 4 + head] = s;
        g_adst1[warp * 4 + head] = d;
    }
}

// ---------------- attention coefficients (layer 2, 1 head x 128) ----------
__global__ void attn_coef2(const float* __restrict__ att_src, const float* __restrict__ att_dst) {
    int warp = (blockIdx.x * blockDim.x + threadIdx.x) >> 5;
    if (warp >= NN) return;
    int lane = threadIdx.x & 31;
    const __half* hrow = g_h2h + (size_t)warp * C2 + lane * 4;
    __half2 hv[2];
    *(int2*)hv = *(const int2*)hrow;
    const float* as_ = att_src + lane * 4;
    const float* ad_ = att_dst + lane * 4;
    float2 f0 = __half22float2(hv[0]), f1 = __half22float2(hv[1]);
    float s = f0.x * as_[0] + f0.y * as_[1] + f1.x * as_[2] + f1.y * as_[3];
    float d = f0.x * ad_[0] + f0.y * ad_[1] + f1.x * ad_[2] + f1.y * ad_[3];
#pragma unroll
    for (int off = 16; off; off >>= 1) {
        s += __shfl_xor_sync(0xffffffffu, s, off);
        d += __shfl_xor_sync(0xffffffffu, d, off);
    }
    if (lane == 0) { g_asrc2[warp] = s; g_adst2[warp] = d; }
}

// ---------------- CSR build -------------------------------------------------
__global__ void degree_kernel(const void* __restrict__ ei) {
    int e = blockIdx.x * blockDim.x + threadIdx.x;
    if (e >= ET) return;
    int is64 = g_is64;
    int d = (e < EE) ? ld_idx(ei, (long long)EE + e, is64) : (e - EE);
    atomicAdd(&g_deg[d], 1);
}

__global__ void scan_phase1() {
    __shared__ int sh[SCAN_B];
    int t = threadIdx.x;
    int i = blockIdx.x * SCAN_B + t;
    sh[t] = (i < NN) ? g_deg[i] : 0;
    __syncthreads();
#pragma unroll
    for (int off = SCAN_B / 2; off; off >>= 1) {
        if (t < off) sh[t] += sh[t + off];
        __syncthreads();
    }
    if (t == 0) g_part[blockIdx.x] = sh[0];
}

__global__ void scan_phase2() {   // 1 block, 128 threads: scan 98 partials
    __shared__ int sh[128];
    int t = threadIdx.x;
    int v = (t < SCAN_G) ? g_part[t] : 0;
    sh[t] = v;
    __syncthreads();
#pragma unroll
    for (int off = 1; off < 128; off <<= 1) {
        int u = (t >= off) ? sh[t - off] : 0;
        __syncthreads();
        sh[t] += u;
        __syncthreads();
    }
    if (t < SCAN_G) g_part[t] = sh[t] - v;   // exclusive
    if (t == 127) g_rowptr[NN] = sh[127];
}

__global__ void scan_phase3() {
    __shared__ int sh[SCAN_B];
    int t = threadIdx.x;
    int i = blockIdx.x * SCAN_B + t;
    int v = (i < NN) ? g_deg[i] : 0;
    sh[t] = v;
    __syncthreads();
#pragma unroll
    for (int off = 1; off < SCAN_B; off <<= 1) {
        int u = (t >= off) ? sh[t - off] : 0;
        __syncthreads();
        sh[t] += u;
        __syncthreads();
    }
    if (i < NN) {
        int ex = g_part[blockIdx.x] + sh[t] - v;
        g_rowptr[i] = ex;
        g_cursor[i] = ex;
    }
}

__global__ void scatter_kernel(const void* __restrict__ ei) {
    int e = blockIdx.x * blockDim.x + threadIdx.x;
    if (e >= ET) return;
    int is64 = g_is64;
    int s, d;
    if (e < EE) { s = ld_idx(ei, e, is64); d = ld_idx(ei, (long long)EE + e, is64); }
    else        { s = e - EE;              d = e - EE; }
    int pos = atomicAdd(&g_cursor[d], 1);
    g_csrsrc[pos] = s;
}

// ---------------- layer-1 aggregation: warp per dst node ------------------
__global__ void aggregate1(const float* __restrict__ b1) {
    int warp = (blockIdx.x * blockDim.x + threadIdx.x) >> 5;
    if (warp >= NN) return;
    int lane = threadIdx.x & 31;
    int head = lane >> 3;
    int start = g_rowptr[warp], end = g_rowptr[warp + 1];
    float4 ad4 = *(const float4*)(g_adst1 + warp * 4);

    // pass 1: per-head max over incoming edges
    float m0 = -1e30f, m1 = -1e30f, m2 = -1e30f, m3 = -1e30f;
    for (int i = start + lane; i < end; i += 32) {
        int s = g_csrsrc[i];
        float4 as4 = *(const float4*)(g_asrc1 + s * 4);
        m0 = fmaxf(m0, lrelu(as4.x + ad4.x));
        m1 = fmaxf(m1, lrelu(as4.y + ad4.y));
        m2 = fmaxf(m2, lrelu(as4.z + ad4.z));
        m3 = fmaxf(m3, lrelu(as4.w + ad4.w));
    }
#pragma unroll
    for (int off = 16; off; off >>= 1) {
        m0 = fmaxf(m0, __shfl_xor_sync(0xffffffffu, m0, off));
        m1 = fmaxf(m1, __shfl_xor_sync(0xffffffffu, m1, off));
        m2 = fmaxf(m2, __shfl_xor_sync(0xffffffffu, m2, off));
        m3 = fmaxf(m3, __shfl_xor_sync(0xffffffffu, m3, off));
    }
    float mh = (head == 0) ? m0 : (head == 1) ? m1 : (head == 2) ? m2 : m3;
    float ad = (head == 0) ? ad4.x : (head == 1) ? ad4.y : (head == 2) ? ad4.z : ad4.w;

    // pass 2: fused exp, denom, weighted fp16 feature gather (2-way unrolled)
    float denom = 0.f;
    float acc[8] = {0.f, 0.f, 0.f, 0.f, 0.f, 0.f, 0.f, 0.f};
    int colbase = lane * 8;
    int i = start;
    for (; i + 1 < end; i += 2) {
        int s0 = g_csrsrc[i], s1 = g_csrsrc[i + 1];
        float a0 = lrelu(g_asrc1[s0 * 4 + head] + ad);
        float a1 = lrelu(g_asrc1[s1 * 4 + head] + ad);
        __half2 u[4], v[4];
        *(int4*)u = *(const int4*)(g_h1h + (size_t)s0 * H1C1 + colbase);
        *(int4*)v = *(const int4*)(g_h1h + (size_t)s1 * H1C1 + colbase);
        float w0 = expf(a0 - mh), w1 = expf(a1 - mh);
        denom += w0 + w1;
#pragma unroll
        for (int k = 0; k < 4; k++) {
            float2 fu = __half22float2(u[k]);
            float2 fv = __half22float2(v[k]);
            acc[2 * k + 0] += w0 * fu.x + w1 * fv.x;
            acc[2 * k + 1] += w0 * fu.y + w1 * fv.y;
        }
    }
    if (i < end) {
        int s0 = g_csrsrc[i];
        float a0 = lrelu(g_asrc1[s0 * 4 + head] + ad);
        float w0 = expf(a0 - mh);
        denom += w0;
        __half2 u[4];
        *(int4*)u = *(const int4*)(g_h1h + (size_t)s0 * H1C1 + colbase);
#pragma unroll
        for (int k = 0; k < 4; k++) {
            float2 fu = __half22float2(u[k]);
            acc[2 * k + 0] += w0 * fu.x;
            acc[2 * k + 1] += w0 * fu.y;
        }
    }
    float inv = 1.f / (denom + 1e-16f);
    const float* bb = b1 + colbase;
    __half o[8];
#pragma unroll
    for (int k = 0; k < 8; k++) o[k] = __float2half(elu(acc[k] * inv + bb[k]));
    *(int4*)(g_out1h + (size_t)warp * H1C1 + colbase) = *(int4*)o;
}

// ---------------- layer-2 aggregation: warp per dst node, 1 head ----------
__global__ void aggregate2(const float* __restrict__ b2) {
    int warp = (blockIdx.x * blockDim.x + threadIdx.x) >> 5;
    if (warp >= NN) return;
    int lane = threadIdx.x & 31;
    int start = g_rowptr[warp], end = g_rowptr[warp + 1];
    float ad = g_adst2[warp];

    float m = -1e30f;
    for (int i = start + lane; i < end; i += 32) {
        int s = g_csrsrc[i];
        m = fmaxf(m, lrelu(g_asrc2[s] + ad));
    }
#pragma unroll
    for (int off = 16; off; off >>= 1)
        m = fmaxf(m, __shfl_xor_sync(0xffffffffu, m, off));

    float denom = 0.f;
    float acc[4] = {0.f, 0.f, 0.f, 0.f};
    int colbase = lane * 4;
    int i = start;
    for (; i + 1 < end; i += 2) {
        int s0 = g_csrsrc[i], s1 = g_csrsrc[i + 1];
        float a0 = lrelu(g_asrc2[s0] + ad);
        float a1 = lrelu(g_asrc2[s1] + ad);
        __half2 u[2], v[2];
        *(int2*)u = *(const int2*)(g_h2h + (size_t)s0 * C2 + colbase);
        *(int2*)v = *(const int2*)(g_h2h + (size_t)s1 * C2 + colbase);
        float w0 = expf(a0 - m), w1 = expf(a1 - m);
        denom += w0 + w1;
#pragma unroll
        for (int k = 0; k < 2; k++) {
            float2 fu = __half22float2(u[k]);
            float2 fv = __half22float2(v[k]);
            acc[2 * k + 0] += w0 * fu.x + w1 * fv.x;
            acc[2 * k + 1] += w0 * fu.y + w1 * fv.y;
        }
    }
    if (i < end) {
        int s0 = g_csrsrc[i];
        float a0 = lrelu(g_asrc2[s0] + ad);
        float w0 = expf(a0 - m);
        denom += w0;
        __half2 u[2];
        *(int2*)u = *(const int2*)(g_h2h + (size_t)s0 * C2 + colbase);
#pragma unroll
        for (int k = 0; k < 2; k++) {
            float2 fu = __half22float2(u[k]);
            acc[2 * k + 0] += w0 * fu.x;
            acc[2 * k + 1] += w0 * fu.y;
        }
    }
    float inv = 1.f / (denom + 1e-16f);
    const float* bb = b2 + colbase;
    float4 o;
    o.x = elu(acc[0] * inv + bb[0]);
    o.y = elu(acc[1] * inv + bb[1]);
    o.z = elu(acc[2] * inv + bb[2]);
    o.w = elu(acc[3] * inv + bb[3]);
    *(float4*)(g_out2 + (size_t)warp * C2 + colbase) = o;
}

// ---------------- pooling ---------------------------------------------------
__global__ void counts_kernel(const void* __restrict__ batch) {
    int n = blockIdx.x * blockDim.x + threadIdx.x;
    if (n < NN) atomicAdd(&g_counts[ld_idx(batch, n, g_is64)], 1);
}

__global__ void pool_kernel(const void* __restrict__ batch) {
    const int NPB = 200;
    int c = threadIdx.x;               // 128 threads = feature dim
    int is64 = g_is64;
    int base = blockIdx.x * NPB;
    int lim = base + NPB < NN ? base + NPB : NN;
    int cur = -1;
    float acc = 0.f;
    for (int n = base; n < lim; n++) {
        int g = ld_idx(batch, n, is64);
        if (g != cur) {
            if (cur >= 0) atomicAdd(&g_pool[cur * C2 + c], acc);
            cur = g; acc = 0.f;
        }
        acc += g_out2[(size_t)n * C2 + c];
    }
    if (cur >= 0) atomicAdd(&g_pool[cur * C2 + c], acc);
}

__global__ void final_kernel(const float* __restrict__ lin_w, const float* __restrict__ lin_b,
                             float* __restrict__ out) {
    int t = threadIdx.x;
    if (t >= NG * NCLS) return;
    int g = t / NCLS, cls = t % NCLS;
    float cnt = fmaxf((float)g_counts[g], 1.f);
    float s = 0.f;
    for (int c = 0; c < C2; c++) s += g_pool[g * C2 + c] * lin_w[c * NCLS + cls];
    out[t] = s / cnt + lin_b[cls];
}

// ---------------- launch ----------------------------------------------------
extern "C" void kernel_launch(void* const* d_in, const int* in_sizes, int n_in,
                              void* d_out, int out_size) {
    const float* x        = (const float*)d_in[0];
    const void*  ei       = d_in[1];               // int32 or int64, detected on device
    const void*  bat      = d_in[2];
    const float* W1       = (const float*)d_in[3];
    const float* att_src1 = (const float*)d_in[4];
    const float* att_dst1 = (const float*)d_in[5];
    const float* b1       = (const float*)d_in[6];
    const float* W2       = (const float*)d_in[7];
    const float* att_src2 = (const float*)d_in[8];
    const float* att_dst2 = (const float*)d_in[9];
    const float* b2       = (const float*)d_in[10];
    const float* lin_w    = (const float*)d_in[11];
    const float* lin_b    = (const float*)d_in[12];
    float* out            = (float*)d_out;

    __half *xh, *w1h, *w2h, *h1h, *out1h, *h2h;
    cudaGetSymbolAddress((void**)&xh, g_xh);
    cudaGetSymbolAddress((void**)&w1h, g_w1h);
    cudaGetSymbolAddress((void**)&w2h, g_w2h);
    cudaGetSymbolAddress((void**)&h1h, g_h1h);
    cudaGetSymbolAddress((void**)&out1h, g_out1h);
    cudaGetSymbolAddress((void**)&h2h, g_h2h);

    // init + dtype detection + fp16 conversions
    detect_kernel<<<1, 32>>>((const unsigned int*)ei);
    zero_kernel<<<(NN + 255) / 256, 256>>>();
    f2h_kernel<<<(NN * FIN / 4 + 255) / 256, 256>>>(x, xh, NN * FIN);
    f2h_kernel<<<(FIN * H1C1 / 4 + 255) / 256, 256>>>(W1, w1h, FIN * H1C1);
    f2h_kernel<<<(H1C1 * C2 / 4 + 255) / 256, 256>>>(W2, w2h, H1C1 * C2);

    // CSR build (graph is same for both layers)
    degree_kernel<<<(ET + 255) / 256, 256>>>(ei);
    scan_phase1<<<SCAN_G, SCAN_B>>>();
    scan_phase2<<<1, 128>>>();
    scan_phase3<<<SCAN_G, SCAN_B>>>();
    scatter_kernel<<<(ET + 255) / 256, 256>>>(ei);

    // layer 1: h1 = x @ W1 (fp16 tensor cores)
    {
        dim3 grid((NN + 127) / 128, H1C1 / 128);
        hgemm128<<<grid, 256>>>(xh, w1h, h1h, NN, H1C1, FIN);
    }
    attn_coef1<<<(NN * 32 + 255) / 256, 256>>>(att_src1, att_dst1);
    aggregate1<<<(NN * 32 + 255) / 256, 256>>>(b1);

    // layer 2: h2 = out1 @ W2
    {
        dim3 grid((NN + 127) / 128, C2 / 128);
        hgemm128<<<grid, 256>>>(out1h, w2h, h2h, NN, C2, H1C1);
    }
    attn_coef2<<<(NN * 32 + 255) / 256, 256>>>(att_src2, att_dst2);
    aggregate2<<<(NN * 32 + 255) / 256, 256>>>(b2);

    // pool + classify
    counts_kernel<<<(NN + 255) / 256, 256>>>(bat);
    pool_kernel<<<(NN + 199) / 200, C2>>>(bat);
    final_kernel<<<1, 256>>>(lin_w, lin_b, out);
}

// round 8
// speedup vs baseline: 1.9048x; 1.1141x over previous
#include <cuda_runtime.h>
#include <cuda_fp16.h>
#include <mma.h>
#include <math.h>

using namespace nvcuda;

// Problem dims
#define NN 50000
#define EE 800000
#define ET 850000      // EE + NN self-loops
#define FIN 128
#define H1C1 256       // 4 heads * 64
#define C2 128
#define NG 32
#define NCLS 5
#define NEG_SLOPE 0.2f

#define SCAN_B 512
#define SCAN_G ((NN + SCAN_B - 1) / SCAN_B)   // 98

// ---------------- scratch (device globals; no allocations allowed) --------
__device__ __half g_w1h[FIN * H1C1];           // W1 fp16
__device__ __half g_w2h[H1C1 * C2];            // W2 fp16
__device__ __half g_h1h[(size_t)NN * H1C1];    // x @ W1  (fp16)
__device__ __half g_out1h[(size_t)NN * H1C1];  // elu(gat1) (fp16, GEMM2 input)
__device__ __half g_h2h[(size_t)NN * C2];      // out1 @ W2 (fp16)
__device__ __half g_out2h[(size_t)NN * C2];    // elu(gat2) (fp16)
__device__ float  g_asrc1[NN * 4], g_adst1[NN * 4];
__device__ float  g_asrc2[NN], g_adst2[NN];
__device__ int    g_deg[NN];
__device__ int    g_rowptr[NN + 1];
__device__ int    g_cursor[NN];
__device__ int    g_csrsrc[ET];
__device__ int    g_part[SCAN_G];
__device__ float  g_pool[NG * C2];
__device__ int    g_counts[NG];
__device__ int    g_is64;

// ---------------- utility -------------------------------------------------
__device__ __forceinline__ float lrelu(float x) { return x > 0.f ? x : NEG_SLOPE * x; }
__device__ __forceinline__ float elu(float x)   { return x > 0.f ? x : (expf(x) - 1.f); }

__device__ __forceinline__ int ld_idx(const void* p, long long i, int is64) {
    if (is64) return (int)((const long long*)p)[i];
    return ((const int*)p)[i];
}

// ---------------- prep: dtype detect + zero init + weight fp16 convert ----
__global__ void prep_kernel(const unsigned int* __restrict__ ei_w,
                            const float* __restrict__ W1,
                            const float* __restrict__ W2) {
    int i = blockIdx.x * blockDim.x + threadIdx.x;
    if (i == 0) {
        unsigned int nz = 0;
        for (int k = 0; k < 128; k++) nz |= ei_w[2 * k + 1];
        g_is64 = (nz == 0u) ? 1 : 0;
    }
    if (i < NN) g_deg[i] = 0;
    if (i < NG * C2) g_pool[i] = 0.f;
    if (i < NG) g_counts[i] = 0;
    if (i < FIN * H1C1) g_w1h[i] = __float2half(W1[i]);
    if (i < H1C1 * C2) g_w2h[i] = __float2half(W2[i]);
}

// ---------------- fp16 WMMA GEMM: C[M,Nn] = A[M,K] * B[K,Nn] ---------------
// Block tile 128x128, BK=32, 256 threads (8 warps: 4 M-warps x 2 N-warps),
// warp tile 32x64 (2x4 wmma 16x16x16 fragments), fp32 accumulate.
// A is fp32 (converted in-register) when AF32, else fp16. C written fp16.
#define ASTRIDE 40
#define BSTRIDE 136
#define CSTRIDE 72
template <bool AF32>
__global__ __launch_bounds__(256) void hgemm128(const void* __restrict__ Ap,
                                                const __half* __restrict__ B,
                                                __half* __restrict__ C,
                                                int M, int Nn, int K) {
    __shared__ __align__(16) unsigned char smem_raw[128 * CSTRIDE * 4];
    __half* As = (__half*)smem_raw;            // 128 x ASTRIDE
    __half* Bs = As + 128 * ASTRIDE;           // 32 x BSTRIDE
    float*  St = (float*)smem_raw;             // epilogue staging 128 x CSTRIDE

    int tid = threadIdx.x;
    int wid = tid >> 5;
    int warp_m = wid & 3;
    int warp_n = wid >> 2;
    int m0 = blockIdx.x * 128, n0 = blockIdx.y * 128;

    wmma::fragment<wmma::accumulator, 16, 16, 16, float> acc[2][4];
#pragma unroll
    for (int i = 0; i < 2; i++)
#pragma unroll
        for (int j = 0; j < 4; j++) wmma::fill_fragment(acc[i][j], 0.f);

    for (int kt = 0; kt < K; kt += 32) {
        // load A tile: 128 rows x 32 halves; 512 chunks of 8 halves (16B)
#pragma unroll
        for (int u = 0; u < 2; u++) {
            int chunk = tid * 2 + u;
            int row = chunk >> 2;
            int c8 = (chunk & 3) * 8;
            if (AF32) {
                const float* A = (const float*)Ap;
                float4 v0 = make_float4(0.f, 0.f, 0.f, 0.f), v1 = v0;
                if (m0 + row < M) {
                    const float* ap = A + (size_t)(m0 + row) * K + kt + c8;
                    v0 = *(const float4*)ap;
                    v1 = *(const float4*)(ap + 4);
                }
                __half h[8] = { __float2half(v0.x), __float2half(v0.y),
                                __float2half(v0.z), __float2half(v0.w),
                                __float2half(v1.x), __float2half(v1.y),
                                __float2half(v1.z), __float2half(v1.w) };
                *(int4*)(As + row * ASTRIDE + c8) = *(int4*)h;
            } else {
                const __half* A = (const __half*)Ap;
                int4 v = make_int4(0, 0, 0, 0);
                if (m0 + row < M) v = *(const int4*)(A + (size_t)(m0 + row) * K + kt + c8);
                *(int4*)(As + row * ASTRIDE + c8) = v;
            }
        }
        // load B tile: 32 rows x 128 halves
#pragma unroll
        for (int u = 0; u < 2; u++) {
            int chunk = tid * 2 + u;
            int row = chunk >> 4;
            int c8 = (chunk & 15) * 8;
            *(int4*)(Bs + row * BSTRIDE + c8) = *(const int4*)(B + (size_t)(kt + row) * Nn + n0 + c8);
        }
        __syncthreads();
#pragma unroll
        for (int kk = 0; kk < 2; kk++) {
            wmma::fragment<wmma::matrix_a, 16, 16, 16, __half, wmma::row_major> af[2];
            wmma::fragment<wmma::matrix_b, 16, 16, 16, __half, wmma::row_major> bf[4];
#pragma unroll
            for (int i = 0; i < 2; i++)
                wmma::load_matrix_sync(af[i], As + (warp_m * 32 + i * 16) * ASTRIDE + kk * 16, ASTRIDE);
#pragma unroll
            for (int j = 0; j < 4; j++)
                wmma::load_matrix_sync(bf[j], Bs + (kk * 16) * BSTRIDE + warp_n * 64 + j * 16, BSTRIDE);
#pragma unroll
            for (int i = 0; i < 2; i++)
#pragma unroll
                for (int j = 0; j < 4; j++)
                    wmma::mma_sync(acc[i][j], af[i], bf[j], acc[i][j]);
        }
        __syncthreads();
    }

    // epilogue: stage fp32 frags to smem per N-half, convert + store fp16
#pragma unroll
    for (int p = 0; p < 2; p++) {
        __syncthreads();
        if (warp_n == p) {
#pragma unroll
            for (int i = 0; i < 2; i++)
#pragma unroll
                for (int j = 0; j < 4; j++)
                    wmma::store_matrix_sync(St + (warp_m * 32 + i * 16) * CSTRIDE + j * 16,
                                            acc[i][j], CSTRIDE, wmma::mem_row_major);
        }
        __syncthreads();
#pragma unroll
        for (int r = 0; r < 4; r++) {
            int row = (tid >> 3) * 4 + r;
            int col = (tid & 7) * 8;
            if (m0 + row < M) {
                const float* sp = St + row * CSTRIDE + col;
                __half h[8];
#pragma unroll
                for (int q = 0; q < 8; q++) h[q] = __float2half(sp[q]);
                *(int4*)(C + (size_t)(m0 + row) * Nn + n0 + p * 64 + col) = *(int4*)h;
            }
        }
    }
}

// ---------------- attention coefficients (layer 1, 4 heads x 64) ----------
__global__ void attn_coef1(const float* __restrict__ att_src, const float* __restrict__ att_dst) {
    int warp = (blockIdx.x * blockDim.x + threadIdx.x) >> 5;
    if (warp >= NN) return;
    int lane = threadIdx.x & 31;
    int head = lane >> 3;
    int lc = (lane & 7) * 8;
    const __half* hrow = g_h1h + (size_t)warp * H1C1 + head * 64 + lc;
    __half2 hv[4];
    *(int4*)hv = *(const int4*)hrow;
    const float* as_ = att_src + head * 64 + lc;
    const float* ad_ = att_dst + head * 64 + lc;
    float s = 0.f, d = 0.f;
#pragma unroll
    for (int k = 0; k < 4; k++) {
        float2 f = __half22float2(hv[k]);
        s += f.x * as_[2 * k] + f.y * as_[2 * k + 1];
        d += f.x * ad_[2 * k] + f.y * ad_[2 * k + 1];
    }
#pragma unroll
    for (int off = 4; off; off >>= 1) {
        s += __shfl_xor_sync(0xffffffffu, s, off);
        d += __shfl_xor_sync(0xffffffffu, d, off);
    }
    if ((lane & 7) == 0) {
        g_asrc1[warp * 4 + head] = s;
        g_adst1[warp * 4 + head] = d;
    }
}

// ---------------- attention coefficients (layer 2, 1 head x 128) ----------
__global__ void attn_coef2(const float* __restrict__ att_src, const float* __restrict__ att_dst) {
    int warp = (blockIdx.x * blockDim.x + threadIdx.x) >> 5;
    if (warp >= NN) return;
    int lane = threadIdx.x & 31;
    const __half* hrow = g_h2h + (size_t)warp * C2 + lane * 4;
    __half2 hv[2];
    *(int2*)hv = *(const int2*)hrow;
    const float* as_ = att_src + lane * 4;
    const float* ad_ = att_dst + lane * 4;
    float2 f0 = __half22float2(hv[0]), f1 = __half22float2(hv[1]);
    float s = f0.x * as_[0] + f0.y * as_[1] + f1.x * as_[2] + f1.y * as_[3];
    float d = f0.x * ad_[0] + f0.y * ad_[1] + f1.x * ad_[2] + f1.y * ad_[3];
#pragma unroll
    for (int off = 16; off; off >>= 1) {
        s += __shfl_xor_sync(0xffffffffu, s, off);
        d += __shfl_xor_sync(0xffffffffu, d, off);
    }
    if (lane == 0) { g_asrc2[warp] = s; g_adst2[warp] = d; }
}

// ---------------- CSR build -------------------------------------------------
__global__ void degree_kernel(const void* __restrict__ ei) {
    int e = blockIdx.x * blockDim.x + threadIdx.x;
    if (e >= ET) return;
    int is64 = g_is64;
    int d = (e < EE) ? ld_idx(ei, (long long)EE + e, is64) : (e - EE);
    atomicAdd(&g_deg[d], 1);
}

__global__ void scan_phase1() {
    __shared__ int sh[SCAN_B];
    int t = threadIdx.x;
    int i = blockIdx.x * SCAN_B + t;
    sh[t] = (i < NN) ? g_deg[i] : 0;
    __syncthreads();
#pragma unroll
    for (int off = SCAN_B / 2; off; off >>= 1) {
        if (t < off) sh[t] += sh[t + off];
        __syncthreads();
    }
    if (t == 0) g_part[blockIdx.x] = sh[0];
}

__global__ void scan_phase2() {   // 1 block, 128 threads: scan 98 partials
    __shared__ int sh[128];
    int t = threadIdx.x;
    int v = (t < SCAN_G) ? g_part[t] : 0;
    sh[t] = v;
    __syncthreads();
#pragma unroll
    for (int off = 1; off < 128; off <<= 1) {
        int u = (t >= off) ? sh[t - off] : 0;
        __syncthreads();
        sh[t] += u;
        __syncthreads();
    }
    if (t < SCAN_G) g_part[t] = sh[t] - v;   // exclusive
    if (t == 127) g_rowptr[NN] = sh[127];
}

__global__ void scan_phase3() {
    __shared__ int sh[SCAN_B];
    int t = threadIdx.x;
    int i = blockIdx.x * SCAN_B + t;
    int v = (i < NN) ? g_deg[i] : 0;
    sh[t] = v;
    __syncthreads();
#pragma unroll
    for (int off = 1; off < SCAN_B; off <<= 1) {
        int u = (t >= off) ? sh[t - off] : 0;
        __syncthreads();
        sh[t] += u;
        __syncthreads();
    }
    if (i < NN) {
        int ex = g_part[blockIdx.x] + sh[t] - v;
        g_rowptr[i] = ex;
        g_cursor[i] = ex;
    }
}

__global__ void scatter_kernel(const void* __restrict__ ei) {
    int e = blockIdx.x * blockDim.x + threadIdx.x;
    if (e >= ET) return;
    int is64 = g_is64;
    int s, d;
    if (e < EE) { s = ld_idx(ei, e, is64); d = ld_idx(ei, (long long)EE + e, is64); }
    else        { s = e - EE;              d = e - EE; }
    int pos = atomicAdd(&g_cursor[d], 1);
    g_csrsrc[pos] = s;
}

// ---------------- layer-1 aggregation: warp per dst node ------------------
// Softmax stabilized with the self-loop alpha (a term of the sum, so denom>=1;
// softmax is shift-invariant, so the result is exact).
__global__ void aggregate1(const float* __restrict__ b1) {
    int warp = (blockIdx.x * blockDim.x + threadIdx.x) >> 5;
    if (warp >= NN) return;
    int lane = threadIdx.x & 31;
    int head = lane >> 3;
    int start = g_rowptr[warp], end = g_rowptr[warp + 1];
    float ad = g_adst1[warp * 4 + head];
    float mh = lrelu(g_asrc1[warp * 4 + head] + ad);   // self-loop alpha

    float denom = 0.f;
    float acc[8] = {0.f, 0.f, 0.f, 0.f, 0.f, 0.f, 0.f, 0.f};
    int colbase = lane * 8;
    int i = start;
    for (; i + 1 < end; i += 2) {
        int s0 = g_csrsrc[i], s1 = g_csrsrc[i + 1];
        float a0 = lrelu(g_asrc1[s0 * 4 + head] + ad);
        float a1 = lrelu(g_asrc1[s1 * 4 + head] + ad);
        __half2 u[4], v[4];
        *(int4*)u = *(const int4*)(g_h1h + (size_t)s0 * H1C1 + colbase);
        *(int4*)v = *(const int4*)(g_h1h + (size_t)s1 * H1C1 + colbase);
        float w0 = expf(a0 - mh), w1 = expf(a1 - mh);
        denom += w0 + w1;
#pragma unroll
        for (int k = 0; k < 4; k++) {
            float2 fu = __half22float2(u[k]);
            float2 fv = __half22float2(v[k]);
            acc[2 * k + 0] += w0 * fu.x + w1 * fv.x;
            acc[2 * k + 1] += w0 * fu.y + w1 * fv.y;
        }
    }
    if (i < end) {
        int s0 = g_csrsrc[i];
        float a0 = lrelu(g_asrc1[s0 * 4 + head] + ad);
        float w0 = expf(a0 - mh);
        denom += w0;
        __half2 u[4];
        *(int4*)u = *(const int4*)(g_h1h + (size_t)s0 * H1C1 + colbase);
#pragma unroll
        for (int k = 0; k < 4; k++) {
            float2 fu = __half22float2(u[k]);
            acc[2 * k + 0] += w0 * fu.x;
            acc[2 * k + 1] += w0 * fu.y;
        }
    }
    float inv = 1.f / (denom + 1e-16f);
    const float* bb = b1 + colbase;
    __half o[8];
#pragma unroll
    for (int k = 0; k < 8; k++) o[k] = __float2half(elu(acc[k] * inv + bb[k]));
    *(int4*)(g_out1h + (size_t)warp * H1C1 + colbase) = *(int4*)o;
}

// ---------------- layer-2 aggregation: warp per dst node, 1 head ----------
__global__ void aggregate2(const float* __restrict__ b2) {
    int warp = (blockIdx.x * blockDim.x + threadIdx.x) >> 5;
    if (warp >= NN) return;
    int lane = threadIdx.x & 31;
    int start = g_rowptr[warp], end = g_rowptr[warp + 1];
    float ad = g_adst2[warp];
    float m = lrelu(g_asrc2[warp] + ad);   // self-loop alpha

    float denom = 0.f;
    float acc[4] = {0.f, 0.f, 0.f, 0.f};
    int colbase = lane * 4;
    int i = start;
    for (; i + 1 < end; i += 2) {
        int s0 = g_csrsrc[i], s1 = g_csrsrc[i + 1];
        float a0 = lrelu(g_asrc2[s0] + ad);
        float a1 = lrelu(g_asrc2[s1] + ad);
        __half2 u[2], v[2];
        *(int2*)u = *(const int2*)(g_h2h + (size_t)s0 * C2 + colbase);
        *(int2*)v = *(const int2*)(g_h2h + (size_t)s1 * C2 + colbase);
        float w0 = expf(a0 - m), w1 = expf(a1 - m);
        denom += w0 + w1;
#pragma unroll
        for (int k = 0; k < 2; k++) {
            float2 fu = __half22float2(u[k]);
            float2 fv = __half22float2(v[k]);
            acc[2 * k + 0] += w0 * fu.x + w1 * fv.x;
            acc[2 * k + 1] += w0 * fu.y + w1 * fv.y;
        }
    }
    if (i < end) {
        int s0 = g_csrsrc[i];
        float a0 = lrelu(g_asrc2[s0] + ad);
        float w0 = expf(a0 - m);
        denom += w0;
        __half2 u[2];
        *(int2*)u = *(const int2*)(g_h2h + (size_t)s0 * C2 + colbase);
#pragma unroll
        for (int k = 0; k < 2; k++) {
            float2 fu = __half22float2(u[k]);
            acc[2 * k + 0] += w0 * fu.x;
            acc[2 * k + 1] += w0 * fu.y;
        }
    }
    float inv = 1.f / (denom + 1e-16f);
    const float* bb = b2 + colbase;
    __half o[4];
    o[0] = __float2half(elu(acc[0] * inv + bb[0]));
    o[1] = __float2half(elu(acc[1] * inv + bb[1]));
    o[2] = __float2half(elu(acc[2] * inv + bb[2]));
    o[3] = __float2half(elu(acc[3] * inv + bb[3]));
    *(int2*)(g_out2h + (size_t)warp * C2 + colbase) = *(int2*)o;
}

// ---------------- pooling (also accumulates per-graph counts) --------------
__global__ void pool_kernel(const void* __restrict__ batch) {
    const int NPB = 200;
    int c = threadIdx.x;               // 128 threads = feature dim
    int is64 = g_is64;
    int base = blockIdx.x * NPB;
    int lim = base + NPB < NN ? base + NPB : NN;
    int cur = -1, rl = 0;
    float acc = 0.f;
    for (int n = base; n < lim; n++) {
        int g = ld_idx(batch, n, is64);
        if (g != cur) {
            if (cur >= 0) {
                atomicAdd(&g_pool[cur * C2 + c], acc);
                if (c == 0) atomicAdd(&g_counts[cur], rl);
            }
            cur = g; acc = 0.f; rl = 0;
        }
        acc += __half2float(g_out2h[(size_t)n * C2 + c]);
        rl++;
    }
    if (cur >= 0) {
        atomicAdd(&g_pool[cur * C2 + c], acc);
        if (c == 0) atomicAdd(&g_counts[cur], rl);
    }
}

__global__ void final_kernel(const float* __restrict__ lin_w, const float* __restrict__ lin_b,
                             float* __restrict__ out) {
    int t = threadIdx.x;
    if (t >= NG * NCLS) return;
    int g = t / NCLS, cls = t % NCLS;
    float cnt = fmaxf((float)g_counts[g], 1.f);
    float s = 0.f;
    for (int c = 0; c < C2; c++) s += g_pool[g * C2 + c] * lin_w[c * NCLS + cls];
    out[t] = s / cnt + lin_b[cls];
}

// ---------------- launch ----------------------------------------------------
extern "C" void kernel_launch(void* const* d_in, const int* in_sizes, int n_in,
                              void* d_out, int out_size) {
    const float* x        = (const float*)d_in[0];
    const void*  ei       = d_in[1];               // int32 or int64, detected on device
    const void*  bat      = d_in[2];
    const float* W1       = (const float*)d_in[3];
    const float* att_src1 = (const float*)d_in[4];
    const float* att_dst1 = (const float*)d_in[5];
    const float* b1       = (const float*)d_in[6];
    const float* W2       = (const float*)d_in[7];
    const float* att_src2 = (const float*)d_in[8];
    const float* att_dst2 = (const float*)d_in[9];
    const float* b2       = (const float*)d_in[10];
    const float* lin_w    = (const float*)d_in[11];
    const float* lin_b    = (const float*)d_in[12];
    float* out            = (float*)d_out;

    __half *w1h, *w2h, *h1h, *out1h, *h2h;
    cudaGetSymbolAddress((void**)&w1h, g_w1h);
    cudaGetSymbolAddress((void**)&w2h, g_w2h);
    cudaGetSymbolAddress((void**)&h1h, g_h1h);
    cudaGetSymbolAddress((void**)&out1h, g_out1h);
    cudaGetSymbolAddress((void**)&h2h, g_h2h);

    // fused init: dtype detect + zero + W1/W2 fp16 convert
    prep_kernel<<<(NN + 255) / 256, 256>>>((const unsigned int*)ei, W1, W2);

    // CSR build (graph is same for both layers)
    degree_kernel<<<(ET + 255) / 256, 256>>>(ei);
    scan_phase1<<<SCAN_G, SCAN_B>>>();
    scan_phase2<<<1, 128>>>();
    scan_phase3<<<SCAN_G, SCAN_B>>>();
    scatter_kernel<<<(ET + 255) / 256, 256>>>(ei);

    // layer 1: h1 = x @ W1 (fp16 tensor cores, A converted in-register)
    {
        dim3 grid((NN + 127) / 128, H1C1 / 128);
        hgemm128<true><<<grid, 256>>>(x, w1h, h1h, NN, H1C1, FIN);
    }
    attn_coef1<<<(NN * 32 + 255) / 256, 256>>>(att_src1, att_dst1);
    aggregate1<<<(NN * 32 + 255) / 256, 256>>>(b1);

    // layer 2: h2 = out1 @ W2
    {
        dim3 grid((NN + 127) / 128, C2 / 128);
        hgemm128<false><<<grid, 256>>>(out1h, w2h, h2h, NN, C2, H1C1);
    }
    attn_coef2<<<(NN * 32 + 255) / 256, 256>>>(att_src2, att_dst2);
    aggregate2<<<(NN * 32 + 255) / 256, 256>>>(b2);

    // pool + classify
    pool_kernel<<<(NN + 199) / 200, C2>>>(bat);
    final_kernel<<<1, 256>>>(lin_w, lin_b, out);
}

// round 10
// speedup vs baseline: 2.0754x; 1.0895x over previous
#include <cuda_runtime.h>
#include <cuda_fp16.h>
#include <mma.h>
#include <math.h>

using namespace nvcuda;

// Problem dims
#define NN 50000
#define EE 800000
#define ET 850000      // EE + NN self-loops
#define FIN 128
#define H1C1 256       // 4 heads * 64
#define C2 128
#define NG 32
#define NCLS 5
#define NEG_SLOPE 0.2f

#define SCAN_B 512
#define SCAN_G ((NN + SCAN_B - 1) / SCAN_B)   // 98

// ---------------- scratch (device globals; no allocations allowed) --------
__device__ __half g_w1h[FIN * H1C1];           // W1 fp16
__device__ __half g_w2h[H1C1 * C2];            // W2 fp16
__device__ __half g_h1h[(size_t)NN * H1C1];    // x @ W1  (fp16)
__device__ __half g_out1h[(size_t)NN * H1C1];  // elu(gat1) (fp16, GEMM2 input)
__device__ __half g_h2h[(size_t)NN * C2];      // out1 @ W2 (fp16)
__device__ __half g_out2h[(size_t)NN * C2];    // elu(gat2) (fp16)
__device__ float  g_asrc1[NN * 4], g_adst1[NN * 4];
__device__ float  g_asrc2[NN], g_adst2[NN];
__device__ int    g_deg[NN];
__device__ int    g_rowptr[NN + 1];
__device__ int    g_cursor[NN];
__device__ int    g_csrsrc[ET];
__device__ int    g_part[SCAN_G];
__device__ float  g_pool[NG * C2];
__device__ int    g_counts[NG];
__device__ int    g_is64;

// ---------------- utility -------------------------------------------------
__device__ __forceinline__ float lrelu(float x) { return x > 0.f ? x : NEG_SLOPE * x; }
__device__ __forceinline__ float elu(float x)   { return x > 0.f ? x : (expf(x) - 1.f); }

__device__ __forceinline__ int ld_idx(const void* p, long long i, int is64) {
    if (is64) return (int)((const long long*)p)[i];
    return ((const int*)p)[i];
}

// ---------------- prep: dtype detect + zero init + weight fp16 convert ----
__global__ void prep_kernel(const unsigned int* __restrict__ ei_w,
                            const float* __restrict__ W1,
                            const float* __restrict__ W2) {
    int i = blockIdx.x * blockDim.x + threadIdx.x;
    if (i == 0) {
        unsigned int nz = 0;
        for (int k = 0; k < 128; k++) nz |= ei_w[2 * k + 1];
        g_is64 = (nz == 0u) ? 1 : 0;
    }
    if (i < NN) g_deg[i] = 0;
    if (i < NG * C2) g_pool[i] = 0.f;
    if (i < NG) g_counts[i] = 0;
    if (i < FIN * H1C1) g_w1h[i] = __float2half(W1[i]);
    if (i < H1C1 * C2) g_w2h[i] = __float2half(W2[i]);
}

// ---------------- fp16 WMMA GEMM: C[M,Nn] = A[M,K] * B[K,Nn] ---------------
// Block tile 128x128, BK=32, 256 threads (8 warps: 4 M-warps x 2 N-warps),
// warp tile 32x64 (2x4 wmma 16x16x16 fragments), fp32 accumulate.
// A is fp32 (converted in-register) when AF32, else fp16. C written fp16.
// MODE 0: plain.  MODE 1: per-64-col-head attention dots -> g_asrc1/g_adst1
// (head = blockIdx.y*2 + p).  MODE 2: single 128-col head -> g_asrc2/g_adst2.
#define ASTRIDE 40
#define BSTRIDE 136
#define CSTRIDE 72
template <bool AF32, int MODE>
__global__ __launch_bounds__(256) void hgemm128(const void* __restrict__ Ap,
                                                const __half* __restrict__ B,
                                                __half* __restrict__ C,
                                                int M, int Nn, int K,
                                                const float* __restrict__ att_src,
                                                const float* __restrict__ att_dst) {
    __shared__ __align__(16) unsigned char smem_raw[128 * CSTRIDE * 4];
    __half* As = (__half*)smem_raw;            // 128 x ASTRIDE
    __half* Bs = As + 128 * ASTRIDE;           // 32 x BSTRIDE
    float*  St = (float*)smem_raw;             // epilogue staging 128 x CSTRIDE

    int tid = threadIdx.x;
    int wid = tid >> 5;
    int warp_m = wid & 3;
    int warp_n = wid >> 2;
    int m0 = blockIdx.x * 128, n0 = blockIdx.y * 128;

    wmma::fragment<wmma::accumulator, 16, 16, 16, float> acc[2][4];
#pragma unroll
    for (int i = 0; i < 2; i++)
#pragma unroll
        for (int j = 0; j < 4; j++) wmma::fill_fragment(acc[i][j], 0.f);

    for (int kt = 0; kt < K; kt += 32) {
#pragma unroll
        for (int u = 0; u < 2; u++) {
            int chunk = tid * 2 + u;
            int row = chunk >> 2;
            int c8 = (chunk & 3) * 8;
            if (AF32) {
                const float* A = (const float*)Ap;
                float4 v0 = make_float4(0.f, 0.f, 0.f, 0.f), v1 = v0;
                if (m0 + row < M) {
                    const float* ap = A + (size_t)(m0 + row) * K + kt + c8;
                    v0 = *(const float4*)ap;
                    v1 = *(const float4*)(ap + 4);
                }
                __half h[8] = { __float2half(v0.x), __float2half(v0.y),
                                __float2half(v0.z), __float2half(v0.w),
                                __float2half(v1.x), __float2half(v1.y),
                                __float2half(v1.z), __float2half(v1.w) };
                *(int4*)(As + row * ASTRIDE + c8) = *(int4*)h;
            } else {
                const __half* A = (const __half*)Ap;
                int4 v = make_int4(0, 0, 0, 0);
                if (m0 + row < M) v = *(const int4*)(A + (size_t)(m0 + row) * K + kt + c8);
                *(int4*)(As + row * ASTRIDE + c8) = v;
            }
        }
#pragma unroll
        for (int u = 0; u < 2; u++) {
            int chunk = tid * 2 + u;
            int row = chunk >> 4;
            int c8 = (chunk & 15) * 8;
            *(int4*)(Bs + row * BSTRIDE + c8) = *(const int4*)(B + (size_t)(kt + row) * Nn + n0 + c8);
        }
        __syncthreads();
#pragma unroll
        for (int kk = 0; kk < 2; kk++) {
            wmma::fragment<wmma::matrix_a, 16, 16, 16, __half, wmma::row_major> af[2];
            wmma::fragment<wmma::matrix_b, 16, 16, 16, __half, wmma::row_major> bf[4];
#pragma unroll
            for (int i = 0; i < 2; i++)
                wmma::load_matrix_sync(af[i], As + (warp_m * 32 + i * 16) * ASTRIDE + kk * 16, ASTRIDE);
#pragma unroll
            for (int j = 0; j < 4; j++)
                wmma::load_matrix_sync(bf[j], Bs + (kk * 16) * BSTRIDE + warp_n * 64 + j * 16, BSTRIDE);
#pragma unroll
            for (int i = 0; i < 2; i++)
#pragma unroll
                for (int j = 0; j < 4; j++)
                    wmma::mma_sync(acc[i][j], af[i], bf[j], acc[i][j]);
        }
        __syncthreads();
    }

    // epilogue: stage fp32 frags to smem per N-half; convert+store fp16;
    // optionally compute attention dots (8-lane group covers 64 cols).
    float sacc[4] = {0.f, 0.f, 0.f, 0.f};
    float dacc[4] = {0.f, 0.f, 0.f, 0.f};
#pragma unroll
    for (int p = 0; p < 2; p++) {
        __syncthreads();
        if (warp_n == p) {
#pragma unroll
            for (int i = 0; i < 2; i++)
#pragma unroll
                for (int j = 0; j < 4; j++)
                    wmma::store_matrix_sync(St + (warp_m * 32 + i * 16) * CSTRIDE + j * 16,
                                            acc[i][j], CSTRIDE, wmma::mem_row_major);
        }
        __syncthreads();
#pragma unroll
        for (int r = 0; r < 4; r++) {
            int row = (tid >> 3) * 4 + r;
            int col = (tid & 7) * 8;
            if (m0 + row < M) {
                const float* sp = St + row * CSTRIDE + col;
                __half h[8];
                float s = 0.f, d = 0.f;
#pragma unroll
                for (int q = 0; q < 8; q++) {
                    float v = sp[q];
                    h[q] = __float2half(v);
                    if (MODE == 1) {
                        s += v * att_src[(blockIdx.y * 2 + p) * 64 + col + q];
                        d += v * att_dst[(blockIdx.y * 2 + p) * 64 + col + q];
                    } else if (MODE == 2) {
                        s += v * att_src[p * 64 + col + q];
                        d += v * att_dst[p * 64 + col + q];
                    }
                }
                *(int4*)(C + (size_t)(m0 + row) * Nn + n0 + p * 64 + col) = *(int4*)h;
                if (MODE == 1) {
                    // reduce over the 8 lanes that share this row (one head)
#pragma unroll
                    for (int off = 4; off; off >>= 1) {
                        s += __shfl_xor_sync(0xffffffffu, s, off);
                        d += __shfl_xor_sync(0xffffffffu, d, off);
                    }
                    if ((tid & 7) == 0) {
                        int head = blockIdx.y * 2 + p;
                        g_asrc1[(m0 + row) * 4 + head] = s;
                        g_adst1[(m0 + row) * 4 + head] = d;
                    }
                } else if (MODE == 2) {
                    sacc[r] += s;
                    dacc[r] += d;
                }
            }
        }
    }
    if (MODE == 2) {
#pragma unroll
        for (int r = 0; r < 4; r++) {
            int row = (tid >> 3) * 4 + r;
            float s = sacc[r], d = dacc[r];
#pragma unroll
            for (int off = 4; off; off >>= 1) {
                s += __shfl_xor_sync(0xffffffffu, s, off);
                d += __shfl_xor_sync(0xffffffffu, d, off);
            }
            if ((tid & 7) == 0 && m0 + row < M) {
                g_asrc2[m0 + row] = s;
                g_adst2[m0 + row] = d;
            }
        }
    }
}

// ---------------- CSR build -------------------------------------------------
__global__ void degree_kernel(const void* __restrict__ ei) {
    int e = blockIdx.x * blockDim.x + threadIdx.x;
    if (e >= ET) return;
    int is64 = g_is64;
    int d = (e < EE) ? ld_idx(ei, (long long)EE + e, is64) : (e - EE);
    atomicAdd(&g_deg[d], 1);
}

__global__ void scan_phase1() {
    __shared__ int sh[SCAN_B];
    int t = threadIdx.x;
    int i = blockIdx.x * SCAN_B + t;
    sh[t] = (i < NN) ? g_deg[i] : 0;
    __syncthreads();
#pragma unroll
    for (int off = SCAN_B / 2; off; off >>= 1) {
        if (t < off) sh[t] += sh[t + off];
        __syncthreads();
    }
    if (t == 0) g_part[blockIdx.x] = sh[0];
}

__global__ void scan_phase2() {   // 1 block, 128 threads: scan 98 partials
    __shared__ int sh[128];
    int t = threadIdx.x;
    int v = (t < SCAN_G) ? g_part[t] : 0;
    sh[t] = v;
    __syncthreads();
#pragma unroll
    for (int off = 1; off < 128; off <<= 1) {
        int u = (t >= off) ? sh[t - off] : 0;
        __syncthreads();
        sh[t] += u;
        __syncthreads();
    }
    if (t < SCAN_G) g_part[t] = sh[t] - v;   // exclusive
    if (t == 127) g_rowptr[NN] = sh[127];
}

__global__ void scan_phase3() {
    __shared__ int sh[SCAN_B];
    int t = threadIdx.x;
    int i = blockIdx.x * SCAN_B + t;
    int v = (i < NN) ? g_deg[i] : 0;
    sh[t] = v;
    __syncthreads();
#pragma unroll
    for (int off = 1; off < SCAN_B; off <<= 1) {
        int u = (t >= off) ? sh[t - off] : 0;
        __syncthreads();
        sh[t] += u;
        __syncthreads();
    }
    if (i < NN) {
        int ex = g_part[blockIdx.x] + sh[t] - v;
        g_rowptr[i] = ex;
        g_cursor[i] = ex;
    }
}

__global__ void scatter_kernel(const void* __restrict__ ei) {
    int e = blockIdx.x * blockDim.x + threadIdx.x;
    if (e >= ET) return;
    int is64 = g_is64;
    int s, d;
    if (e < EE) { s = ld_idx(ei, e, is64); d = ld_idx(ei, (long long)EE + e, is64); }
    else        { s = e - EE;              d = e - EE; }
    int pos = atomicAdd(&g_cursor[d], 1);
    g_csrsrc[pos] = s;
}

// ---------------- layer-1 aggregation: warp per dst node ------------------
// Softmax stabilized with the self-loop alpha (a term of the sum, so denom>=1;
// softmax is shift-invariant, so the result is exact). 4-way unrolled for MLP.
__global__ void aggregate1(const float* __restrict__ b1) {
    int warp = (blockIdx.x * blockDim.x + threadIdx.x) >> 5;
    if (warp >= NN) return;
    int lane = threadIdx.x & 31;
    int head = lane >> 3;
    int start = g_rowptr[warp], end = g_rowptr[warp + 1];
    float ad = g_adst1[warp * 4 + head];
    float mh = lrelu(g_asrc1[warp * 4 + head] + ad);   // self-loop alpha

    float denom = 0.f;
    float acc[8] = {0.f, 0.f, 0.f, 0.f, 0.f, 0.f, 0.f, 0.f};
    int colbase = lane * 8;
    int i = start;
    for (; i + 3 < end; i += 4) {
        int s0 = g_csrsrc[i], s1 = g_csrsrc[i + 1], s2 = g_csrsrc[i + 2], s3 = g_csrsrc[i + 3];
        float a0 = g_asrc1[s0 * 4 + head];
        float a1 = g_asrc1[s1 * 4 + head];
        float a2 = g_asrc1[s2 * 4 + head];
        float a3 = g_asrc1[s3 * 4 + head];
        __half2 u0[4], u1[4], u2[4], u3[4];
        *(int4*)u0 = *(const int4*)(g_h1h + (size_t)s0 * H1C1 + colbase);
        *(int4*)u1 = *(const int4*)(g_h1h + (size_t)s1 * H1C1 + colbase);
        *(int4*)u2 = *(const int4*)(g_h1h + (size_t)s2 * H1C1 + colbase);
        *(int4*)u3 = *(const int4*)(g_h1h + (size_t)s3 * H1C1 + colbase);
        float w0 = expf(lrelu(a0 + ad) - mh);
        float w1 = expf(lrelu(a1 + ad) - mh);
        float w2 = expf(lrelu(a2 + ad) - mh);
        float w3 = expf(lrelu(a3 + ad) - mh);
        denom += (w0 + w1) + (w2 + w3);
#pragma unroll
        for (int k = 0; k < 4; k++) {
            float2 f0 = __half22float2(u0[k]);
            float2 f1 = __half22float2(u1[k]);
            float2 f2 = __half22float2(u2[k]);
            float2 f3 = __half22float2(u3[k]);
            acc[2 * k + 0] += (w0 * f0.x + w1 * f1.x) + (w2 * f2.x + w3 * f3.x);
            acc[2 * k + 1] += (w0 * f0.y + w1 * f1.y) + (w2 * f2.y + w3 * f3.y);
        }
    }
    for (; i < end; i++) {
        int s0 = g_csrsrc[i];
        float w0 = expf(lrelu(g_asrc1[s0 * 4 + head] + ad) - mh);
        denom += w0;
        __half2 u[4];
        *(int4*)u = *(const int4*)(g_h1h + (size_t)s0 * H1C1 + colbase);
#pragma unroll
        for (int k = 0; k < 4; k++) {
            float2 fu = __half22float2(u[k]);
            acc[2 * k + 0] += w0 * fu.x;
            acc[2 * k + 1] += w0 * fu.y;
        }
    }
    float inv = 1.f / (denom + 1e-16f);
    const float* bb = b1 + colbase;
    __half o[8];
#pragma unroll
    for (int k = 0; k < 8; k++) o[k] = __float2half(elu(acc[k] * inv + bb[k]));
    *(int4*)(g_out1h + (size_t)warp * H1C1 + colbase) = *(int4*)o;
}

// ---------------- layer-2 aggregation: warp per dst node, 1 head ----------
__global__ void aggregate2(const float* __restrict__ b2) {
    int warp = (blockIdx.x * blockDim.x + threadIdx.x) >> 5;
    if (warp >= NN) return;
    int lane = threadIdx.x & 31;
    int start = g_rowptr[warp], end = g_rowptr[warp + 1];
    float ad = g_adst2[warp];
    float m = lrelu(g_asrc2[warp] + ad);   // self-loop alpha

    float denom = 0.f;
    float acc[4] = {0.f, 0.f, 0.f, 0.f};
    int colbase = lane * 4;
    int i = start;
    for (; i + 3 < end; i += 4) {
        int s0 = g_csrsrc[i], s1 = g_csrsrc[i + 1], s2 = g_csrsrc[i + 2], s3 = g_csrsrc[i + 3];
        float a0 = g_asrc2[s0], a1 = g_asrc2[s1], a2 = g_asrc2[s2], a3 = g_asrc2[s3];
        __half2 u0[2], u1[2], u2[2], u3[2];
        *(int2*)u0 = *(const int2*)(g_h2h + (size_t)s0 * C2 + colbase);
        *(int2*)u1 = *(const int2*)(g_h2h + (size_t)s1 * C2 + colbase);
        *(int2*)u2 = *(const int2*)(g_h2h + (size_t)s2 * C2 + colbase);
        *(int2*)u3 = *(const int2*)(g_h2h + (size_t)s3 * C2 + colbase);
        float w0 = expf(lrelu(a0 + ad) - m);
        float w1 = expf(lrelu(a1 + ad) - m);
        float w2 = expf(lrelu(a2 + ad) - m);
        float w3 = expf(lrelu(a3 + ad) - m);
        denom += (w0 + w1) + (w2 + w3);
#pragma unroll
        for (int k = 0; k < 2; k++) {
            float2 f0 = __half22float2(u0[k]);
            float2 f1 = __half22float2(u1[k]);
            float2 f2 = __half22float2(u2[k]);
            float2 f3 = __half22float2(u3[k]);
            acc[2 * k + 0] += (w0 * f0.x + w1 * f1.x) + (w2 * f2.x + w3 * f3.x);
            acc[2 * k + 1] += (w0 * f0.y + w1 * f1.y) + (w2 * f2.y + w3 * f3.y);
        }
    }
    for (; i < end; i++) {
        int s0 = g_csrsrc[i];
        float w0 = expf(lrelu(g_asrc2[s0] + ad) - m);
        denom += w0;
        __half2 u[2];
        *(int2*)u = *(const int2*)(g_h2h + (size_t)s0 * C2 + colbase);
#pragma unroll
        for (int k = 0; k < 2; k++) {
            float2 fu = __half22float2(u[k]);
            acc[2 * k + 0] += w0 * fu.x;
            acc[2 * k + 1] += w0 * fu.y;
        }
    }
    float inv = 1.f / (denom + 1e-16f);
    const float* bb = b2 + colbase;
    __half o[4];
    o[0] = __float2half(elu(acc[0] * inv + bb[0]));
    o[1] = __float2half(elu(acc[1] * inv + bb[1]));
    o[2] = __float2half(elu(acc[2] * inv + bb[2]));
    o[3] = __float2half(elu(acc[3] * inv + bb[3]));
    *(int2*)(g_out2h + (size_t)warp * C2 + colbase) = *(int2*)o;
}

// ---------------- pooling (also accumulates per-graph counts) --------------
__global__ void pool_kernel(const void* __restrict__ batch) {
    const int NPB = 200;
    int c = threadIdx.x;               // 128 threads = feature dim
    int is64 = g_is64;
    int base = blockIdx.x * NPB;
    int lim = base + NPB < NN ? base + NPB : NN;
    int cur = -1, rl = 0;
    float acc = 0.f;
    for (int n = base; n < lim; n++) {
        int g = ld_idx(batch, n, is64);
        if (g != cur) {
            if (cur >= 0) {
                atomicAdd(&g_pool[cur * C2 + c], acc);
                if (c == 0) atomicAdd(&g_counts[cur], rl);
            }
            cur = g; acc = 0.f; rl = 0;
        }
        acc += __half2float(g_out2h[(size_t)n * C2 + c]);
        rl++;
    }
    if (cur >= 0) {
        atomicAdd(&g_pool[cur * C2 + c], acc);
        if (c == 0) atomicAdd(&g_counts[cur], rl);
    }
}

__global__ void final_kernel(const float* __restrict__ lin_w, const float* __restrict__ lin_b,
                             float* __restrict__ out) {
    int t = threadIdx.x;
    if (t >= NG * NCLS) return;
    int g = t / NCLS, cls = t % NCLS;
    float cnt = fmaxf((float)g_counts[g], 1.f);
    float s = 0.f;
    for (int c = 0; c < C2; c++) s += g_pool[g * C2 + c] * lin_w[c * NCLS + cls];
    out[t] = s / cnt + lin_b[cls];
}

// ---------------- launch ----------------------------------------------------
extern "C" void kernel_launch(void* const* d_in, const int* in_sizes, int n_in,
                              void* d_out, int out_size) {
    const float* x        = (const float*)d_in[0];
    const void*  ei       = d_in[1];               // int32 or int64, detected on device
    const void*  bat      = d_in[2];
    const float* W1       = (const float*)d_in[3];
    const float* att_src1 = (const float*)d_in[4];
    const float* att_dst1 = (const float*)d_in[5];
    const float* b1       = (const float*)d_in[6];
    const float* W2       = (const float*)d_in[7];
    const float* att_src2 = (const float*)d_in[8];
    const float* att_dst2 = (const float*)d_in[9];
    const float* b2       = (const float*)d_in[10];
    const float* lin_w    = (const float*)d_in[11];
    const float* lin_b    = (const float*)d_in[12];
    float* out            = (float*)d_out;

    __half *w1h, *w2h, *h1h, *out1h, *h2h;
    cudaGetSymbolAddress((void**)&w1h, g_w1h);
    cudaGetSymbolAddress((void**)&w2h, g_w2h);
    cudaGetSymbolAddress((void**)&h1h, g_h1h);
    cudaGetSymbolAddress((void**)&out1h, g_out1h);
    cudaGetSymbolAddress((void**)&h2h, g_h2h);

    // fused init: dtype detect + zero + W1/W2 fp16 convert
    prep_kernel<<<(NN + 255) / 256, 256>>>((const unsigned int*)ei, W1, W2);

    // CSR build (graph is same for both layers)
    degree_kernel<<<(ET + 255) / 256, 256>>>(ei);
    scan_phase1<<<SCAN_G, SCAN_B>>>();
    scan_phase2<<<1, 128>>>();
    scan_phase3<<<SCAN_G, SCAN_B>>>();
    scatter_kernel<<<(ET + 255) / 256, 256>>>(ei);

    // layer 1: h1 = x @ W1 (fp16 tensor cores, A converted in-register,
    // attention coefficients fused into the epilogue)
    {
        dim3 grid((NN + 127) / 128, H1C1 / 128);
        hgemm128<true, 1><<<grid, 256>>>(x, w1h, h1h, NN, H1C1, FIN, att_src1, att_dst1);
    }
    aggregate1<<<(NN * 32 + 255) / 256, 256>>>(b1);

    // layer 2: h2 = out1 @ W2 (attention fused)
    {
        dim3 grid((NN + 127) / 128, C2 / 128);
        hgemm128<false, 2><<<grid, 256>>>(out1h, w2h, h2h, NN, C2, H1C1, att_src2, att_dst2);
    }
    aggregate2<<<(NN * 32 + 255) / 256, 256>>>(b2);

    // pool + classify
    pool_kernel<<<(NN + 199) / 200, C2>>>(bat);
    final_kernel<<<1, 256>>>(lin_w, lin_b, out);
}

// round 11
// speedup vs baseline: 2.0990x; 1.0114x over previous
#include <cuda_runtime.h>
#include <cuda_fp16.h>
#include <mma.h>
#include <math.h>

using namespace nvcuda;

// Problem dims
#define NN 50000
#define EE 800000
#define ET 850000      // EE + NN self-loops
#define FIN 128
#define H1C1 256       // 4 heads * 64
#define C2 128
#define NG 32
#define NCLS 5
#define NEG_SLOPE 0.2f

#define SCAN_B 512
#define SCAN_G ((NN + SCAN_B - 1) / SCAN_B)   // 98

// ---------------- scratch (device globals; no allocations allowed) --------
__device__ __half g_h1h[(size_t)NN * H1C1];    // x @ W1  (fp16)
__device__ __half g_out1h[(size_t)NN * H1C1];  // elu(gat1) (fp16, GEMM2 input)
__device__ __half g_h2h[(size_t)NN * C2];      // out1 @ W2 (fp16)
__device__ __half g_out2h[(size_t)NN * C2];    // elu(gat2) (fp16)
__device__ float  g_asrc1[NN * 4], g_adst1[NN * 4];
__device__ float  g_asrc2[NN], g_adst2[NN];
__device__ int    g_deg[NN];
__device__ int    g_rowptr[NN + 1];
__device__ int    g_cursor[NN];
__device__ int    g_csrsrc[ET];
__device__ int    g_part[SCAN_G];
__device__ float  g_pool[NG * C2];
__device__ int    g_counts[NG];
__device__ int    g_is64;

// ---------------- utility -------------------------------------------------
__device__ __forceinline__ float lrelu(float x) { return x > 0.f ? x : NEG_SLOPE * x; }
__device__ __forceinline__ float elu(float x)   { return x > 0.f ? x : (expf(x) - 1.f); }

__device__ __forceinline__ int ld_idx(const void* p, long long i, int is64) {
    if (is64) return (int)((const long long*)p)[i];
    return ((const int*)p)[i];
}

// ---------------- prep: dtype detect + zero init ---------------------------
__global__ void prep_kernel(const unsigned int* __restrict__ ei_w) {
    int i = blockIdx.x * blockDim.x + threadIdx.x;
    if (i == 0) {
        unsigned int nz = 0;
        for (int k = 0; k < 128; k++) nz |= ei_w[2 * k + 1];
        g_is64 = (nz == 0u) ? 1 : 0;
    }
    if (i < NN) g_deg[i] = 0;
    if (i < NG * C2) g_pool[i] = 0.f;
    if (i < NG) g_counts[i] = 0;
}

// ---------------- fp16 WMMA GEMM: C[M,Nn] = A[M,K] * B[K,Nn] ---------------
// Block tile 128x128, BK=32, 256 threads (8 warps: 4 M-warps x 2 N-warps),
// warp tile 32x64 (2x4 wmma 16x16x16 fragments), fp32 accumulate.
// A / B fp32 are converted in-register when AF32 / BF32. C written fp16.
// MODE 1: per-64-col-head attention dots -> g_asrc1/g_adst1 (head=by*2+p).
// MODE 2: single 128-col head -> g_asrc2/g_adst2.
#define ASTRIDE 40
#define BSTRIDE 136
#define CSTRIDE 72
template <bool AF32, bool BF32, int MODE>
__global__ __launch_bounds__(256) void hgemm128(const void* __restrict__ Ap,
                                                const void* __restrict__ Bp,
                                                __half* __restrict__ C,
                                                int M, int Nn, int K,
                                                const float* __restrict__ att_src,
                                                const float* __restrict__ att_dst) {
    __shared__ __align__(16) unsigned char smem_raw[128 * CSTRIDE * 4];
    __half* As = (__half*)smem_raw;            // 128 x ASTRIDE
    __half* Bs = As + 128 * ASTRIDE;           // 32 x BSTRIDE
    float*  St = (float*)smem_raw;             // epilogue staging 128 x CSTRIDE

    int tid = threadIdx.x;
    int wid = tid >> 5;
    int warp_m = wid & 3;
    int warp_n = wid >> 2;
    int m0 = blockIdx.x * 128, n0 = blockIdx.y * 128;

    wmma::fragment<wmma::accumulator, 16, 16, 16, float> acc[2][4];
#pragma unroll
    for (int i = 0; i < 2; i++)
#pragma unroll
        for (int j = 0; j < 4; j++) wmma::fill_fragment(acc[i][j], 0.f);

    for (int kt = 0; kt < K; kt += 32) {
        // A tile: 128 rows x 32 halves
#pragma unroll
        for (int u = 0; u < 2; u++) {
            int chunk = tid * 2 + u;
            int row = chunk >> 2;
            int c8 = (chunk & 3) * 8;
            if (AF32) {
                const float* A = (const float*)Ap;
                float4 v0 = make_float4(0.f, 0.f, 0.f, 0.f), v1 = v0;
                if (m0 + row < M) {
                    const float* ap = A + (size_t)(m0 + row) * K + kt + c8;
                    v0 = *(const float4*)ap;
                    v1 = *(const float4*)(ap + 4);
                }
                __half h[8] = { __float2half(v0.x), __float2half(v0.y),
                                __float2half(v0.z), __float2half(v0.w),
                                __float2half(v1.x), __float2half(v1.y),
                                __float2half(v1.z), __float2half(v1.w) };
                *(int4*)(As + row * ASTRIDE + c8) = *(int4*)h;
            } else {
                const __half* A = (const __half*)Ap;
                int4 v = make_int4(0, 0, 0, 0);
                if (m0 + row < M) v = *(const int4*)(A + (size_t)(m0 + row) * K + kt + c8);
                *(int4*)(As + row * ASTRIDE + c8) = v;
            }
        }
        // B tile: 32 rows x 128 halves
#pragma unroll
        for (int u = 0; u < 2; u++) {
            int chunk = tid * 2 + u;
            int row = chunk >> 4;
            int c8 = (chunk & 15) * 8;
            if (BF32) {
                const float* B = (const float*)Bp;
                const float* bp = B + (size_t)(kt + row) * Nn + n0 + c8;
                float4 v0 = *(const float4*)bp;
                float4 v1 = *(const float4*)(bp + 4);
                __half h[8] = { __float2half(v0.x), __float2half(v0.y),
                                __float2half(v0.z), __float2half(v0.w),
                                __float2half(v1.x), __float2half(v1.y),
                                __float2half(v1.z), __float2half(v1.w) };
                *(int4*)(Bs + row * BSTRIDE + c8) = *(int4*)h;
            } else {
                const __half* B = (const __half*)Bp;
                *(int4*)(Bs + row * BSTRIDE + c8) = *(const int4*)(B + (size_t)(kt + row) * Nn + n0 + c8);
            }
        }
        __syncthreads();
#pragma unroll
        for (int kk = 0; kk < 2; kk++) {
            wmma::fragment<wmma::matrix_a, 16, 16, 16, __half, wmma::row_major> af[2];
            wmma::fragment<wmma::matrix_b, 16, 16, 16, __half, wmma::row_major> bf[4];
#pragma unroll
            for (int i = 0; i < 2; i++)
                wmma::load_matrix_sync(af[i], As + (warp_m * 32 + i * 16) * ASTRIDE + kk * 16, ASTRIDE);
#pragma unroll
            for (int j = 0; j < 4; j++)
                wmma::load_matrix_sync(bf[j], Bs + (kk * 16) * BSTRIDE + warp_n * 64 + j * 16, BSTRIDE);
#pragma unroll
            for (int i = 0; i < 2; i++)
#pragma unroll
                for (int j = 0; j < 4; j++)
                    wmma::mma_sync(acc[i][j], af[i], bf[j], acc[i][j]);
        }
        __syncthreads();
    }

    // epilogue: stage fp32 frags per N-half; convert+store fp16; fused attn dots
    float sacc[4] = {0.f, 0.f, 0.f, 0.f};
    float dacc[4] = {0.f, 0.f, 0.f, 0.f};
#pragma unroll
    for (int p = 0; p < 2; p++) {
        __syncthreads();
        if (warp_n == p) {
#pragma unroll
            for (int i = 0; i < 2; i++)
#pragma unroll
                for (int j = 0; j < 4; j++)
                    wmma::store_matrix_sync(St + (warp_m * 32 + i * 16) * CSTRIDE + j * 16,
                                            acc[i][j], CSTRIDE, wmma::mem_row_major);
        }
        __syncthreads();
#pragma unroll
        for (int r = 0; r < 4; r++) {
            int row = (tid >> 3) * 4 + r;
            int col = (tid & 7) * 8;
            if (m0 + row < M) {
                const float* sp = St + row * CSTRIDE + col;
                __half h[8];
                float s = 0.f, d = 0.f;
#pragma unroll
                for (int q = 0; q < 8; q++) {
                    float v = sp[q];
                    h[q] = __float2half(v);
                    if (MODE == 1) {
                        s += v * att_src[(blockIdx.y * 2 + p) * 64 + col + q];
                        d += v * att_dst[(blockIdx.y * 2 + p) * 64 + col + q];
                    } else if (MODE == 2) {
                        s += v * att_src[p * 64 + col + q];
                        d += v * att_dst[p * 64 + col + q];
                    }
                }
                *(int4*)(C + (size_t)(m0 + row) * Nn + n0 + p * 64 + col) = *(int4*)h;
                if (MODE == 1) {
#pragma unroll
                    for (int off = 4; off; off >>= 1) {
                        s += __shfl_xor_sync(0xffffffffu, s, off);
                        d += __shfl_xor_sync(0xffffffffu, d, off);
                    }
                    if ((tid & 7) == 0) {
                        int head = blockIdx.y * 2 + p;
                        g_asrc1[(m0 + row) * 4 + head] = s;
                        g_adst1[(m0 + row) * 4 + head] = d;
                    }
                } else if (MODE == 2) {
                    sacc[r] += s;
                    dacc[r] += d;
                }
            }
        }
    }
    if (MODE == 2) {
#pragma unroll
        for (int r = 0; r < 4; r++) {
            int row = (tid >> 3) * 4 + r;
            float s = sacc[r], d = dacc[r];
#pragma unroll
            for (int off = 4; off; off >>= 1) {
                s += __shfl_xor_sync(0xffffffffu, s, off);
                d += __shfl_xor_sync(0xffffffffu, d, off);
            }
            if ((tid & 7) == 0 && m0 + row < M) {
                g_asrc2[m0 + row] = s;
                g_adst2[m0 + row] = d;
            }
        }
    }
}

// ---------------- CSR build -------------------------------------------------
__global__ void degree_kernel(const void* __restrict__ ei) {
    int e = blockIdx.x * blockDim.x + threadIdx.x;
    if (e >= ET) return;
    int is64 = g_is64;
    int d = (e < EE) ? ld_idx(ei, (long long)EE + e, is64) : (e - EE);
    atomicAdd(&g_deg[d], 1);
}

__global__ void scan_phase1() {
    __shared__ int sh[SCAN_B];
    int t = threadIdx.x;
    int i = blockIdx.x * SCAN_B + t;
    sh[t] = (i < NN) ? g_deg[i] : 0;
    __syncthreads();
#pragma unroll
    for (int off = SCAN_B / 2; off; off >>= 1) {
        if (t < off) sh[t] += sh[t + off];
        __syncthreads();
    }
    if (t == 0) g_part[blockIdx.x] = sh[0];
}

__global__ void scan_phase2() {   // 1 block, 128 threads: scan 98 partials
    __shared__ int sh[128];
    int t = threadIdx.x;
    int v = (t < SCAN_G) ? g_part[t] : 0;
    sh[t] = v;
    __syncthreads();
#pragma unroll
    for (int off = 1; off < 128; off <<= 1) {
        int u = (t >= off) ? sh[t - off] : 0;
        __syncthreads();
        sh[t] += u;
        __syncthreads();
    }
    if (t < SCAN_G) g_part[t] = sh[t] - v;   // exclusive
    if (t == 127) g_rowptr[NN] = sh[127];
}

__global__ void scan_phase3() {
    __shared__ int sh[SCAN_B];
    int t = threadIdx.x;
    int i = blockIdx.x * SCAN_B + t;
    int v = (i < NN) ? g_deg[i] : 0;
    sh[t] = v;
    __syncthreads();
#pragma unroll
    for (int off = 1; off < SCAN_B; off <<= 1) {
        int u = (t >= off) ? sh[t - off] : 0;
        __syncthreads();
        sh[t] += u;
        __syncthreads();
    }
    if (i < NN) {
        int ex = g_part[blockIdx.x] + sh[t] - v;
        g_rowptr[i] = ex;
        g_cursor[i] = ex;
    }
}

__global__ void scatter_kernel(const void* __restrict__ ei) {
    int e = blockIdx.x * blockDim.x + threadIdx.x;
    if (e >= ET) return;
    int is64 = g_is64;
    int s, d;
    if (e < EE) { s = ld_idx(ei, e, is64); d = ld_idx(ei, (long long)EE + e, is64); }
    else        { s = e - EE;              d = e - EE; }
    int pos = atomicAdd(&g_cursor[d], 1);
    g_csrsrc[pos] = s;
}

// ---------------- layer-1 aggregation: warp per dst node ------------------
// Softmax stabilized with the self-loop alpha (a term of the sum, so denom>=1;
// softmax is shift-invariant, so the result is exact). 4-way unrolled for MLP.
__global__ void aggregate1(const float* __restrict__ b1) {
    int warp = (blockIdx.x * blockDim.x + threadIdx.x) >> 5;
    if (warp >= NN) return;
    int lane = threadIdx.x & 31;
    int head = lane >> 3;
    int start = g_rowptr[warp], end = g_rowptr[warp + 1];
    float ad = g_adst1[warp * 4 + head];
    float mh = lrelu(g_asrc1[warp * 4 + head] + ad);   // self-loop alpha

    float denom = 0.f;
    float acc[8] = {0.f, 0.f, 0.f, 0.f, 0.f, 0.f, 0.f, 0.f};
    int colbase = lane * 8;
    int i = start;
    for (; i + 3 < end; i += 4) {
        int s0 = g_csrsrc[i], s1 = g_csrsrc[i + 1], s2 = g_csrsrc[i + 2], s3 = g_csrsrc[i + 3];
        float a0 = g_asrc1[s0 * 4 + head];
        float a1 = g_asrc1[s1 * 4 + head];
        float a2 = g_asrc1[s2 * 4 + head];
        float a3 = g_asrc1[s3 * 4 + head];
        __half2 u0[4], u1[4], u2[4], u3[4];
        *(int4*)u0 = *(const int4*)(g_h1h + (size_t)s0 * H1C1 + colbase);
        *(int4*)u1 = *(const int4*)(g_h1h + (size_t)s1 * H1C1 + colbase);
        *(int4*)u2 = *(const int4*)(g_h1h + (size_t)s2 * H1C1 + colbase);
        *(int4*)u3 = *(const int4*)(g_h1h + (size_t)s3 * H1C1 + colbase);
        float w0 = expf(lrelu(a0 + ad) - mh);
        float w1 = expf(lrelu(a1 + ad) - mh);
        float w2 = expf(lrelu(a2 + ad) - mh);
        float w3 = expf(lrelu(a3 + ad) - mh);
        denom += (w0 + w1) + (w2 + w3);
#pragma unroll
        for (int k = 0; k < 4; k++) {
            float2 f0 = __half22float2(u0[k]);
            float2 f1 = __half22float2(u1[k]);
            float2 f2 = __half22float2(u2[k]);
            float2 f3 = __half22float2(u3[k]);
            acc[2 * k + 0] += (w0 * f0.x + w1 * f1.x) + (w2 * f2.x + w3 * f3.x);
            acc[2 * k + 1] += (w0 * f0.y + w1 * f1.y) + (w2 * f2.y + w3 * f3.y);
        }
    }
    for (; i < end; i++) {
        int s0 = g_csrsrc[i];
        float w0 = expf(lrelu(g_asrc1[s0 * 4 + head] + ad) - mh);
        denom += w0;
        __half2 u[4];
        *(int4*)u = *(const int4*)(g_h1h + (size_t)s0 * H1C1 + colbase);
#pragma unroll
        for (int k = 0; k < 4; k++) {
            float2 fu = __half22float2(u[k]);
            acc[2 * k + 0] += w0 * fu.x;
            acc[2 * k + 1] += w0 * fu.y;
        }
    }
    float inv = 1.f / (denom + 1e-16f);
    const float* bb = b1 + colbase;
    __half o[8];
#pragma unroll
    for (int k = 0; k < 8; k++) o[k] = __float2half(elu(acc[k] * inv + bb[k]));
    *(int4*)(g_out1h + (size_t)warp * H1C1 + colbase) = *(int4*)o;
}

// ---------------- layer-2 aggregation: warp per dst node, 1 head ----------
__global__ void aggregate2(const float* __restrict__ b2) {
    int warp = (blockIdx.x * blockDim.x + threadIdx.x) >> 5;
    if (warp >= NN) return;
    int lane = threadIdx.x & 31;
    int start = g_rowptr[warp], end = g_rowptr[warp + 1];
    float ad = g_adst2[warp];
    float m = lrelu(g_asrc2[warp] + ad);   // self-loop alpha

    float denom = 0.f;
    float acc[4] = {0.f, 0.f, 0.f, 0.f};
    int colbase = lane * 4;
    int i = start;
    for (; i + 3 < end; i += 4) {
        int s0 = g_csrsrc[i], s1 = g_csrsrc[i + 1], s2 = g_csrsrc[i + 2], s3 = g_csrsrc[i + 3];
        float a0 = g_asrc2[s0], a1 = g_asrc2[s1], a2 = g_asrc2[s2], a3 = g_asrc2[s3];
        __half2 u0[2], u1[2], u2[2], u3[2];
        *(int2*)u0 = *(const int2*)(g_h2h + (size_t)s0 * C2 + colbase);
        *(int2*)u1 = *(const int2*)(g_h2h + (size_t)s1 * C2 + colbase);
        *(int2*)u2 = *(const int2*)(g_h2h + (size_t)s2 * C2 + colbase);
        *(int2*)u3 = *(const int2*)(g_h2h + (size_t)s3 * C2 + colbase);
        float w0 = expf(lrelu(a0 + ad) - m);
        float w1 = expf(lrelu(a1 + ad) - m);
        float w2 = expf(lrelu(a2 + ad) - m);
        float w3 = expf(lrelu(a3 + ad) - m);
        denom += (w0 + w1) + (w2 + w3);
#pragma unroll
        for (int k = 0; k < 2; k++) {
            float2 f0 = __half22float2(u0[k]);
            float2 f1 = __half22float2(u1[k]);
            float2 f2 = __half22float2(u2[k]);
            float2 f3 = __half22float2(u3[k]);
            acc[2 * k + 0] += (w0 * f0.x + w1 * f1.x) + (w2 * f2.x + w3 * f3.x);
            acc[2 * k + 1] += (w0 * f0.y + w1 * f1.y) + (w2 * f2.y + w3 * f3.y);
        }
    }
    for (; i < end; i++) {
        int s0 = g_csrsrc[i];
        float w0 = expf(lrelu(g_asrc2[s0] + ad) - m);
        denom += w0;
        __half2 u[2];
        *(int2*)u = *(const int2*)(g_h2h + (size_t)s0 * C2 + colbase);
#pragma unroll
        for (int k = 0; k < 2; k++) {
            float2 fu = __half22float2(u[k]);
            acc[2 * k + 0] += w0 * fu.x;
            acc[2 * k + 1] += w0 * fu.y;
        }
    }
    float inv = 1.f / (denom + 1e-16f);
    const float* bb = b2 + colbase;
    __half o[4];
    o[0] = __float2half(elu(acc[0] * inv + bb[0]));
    o[1] = __float2half(elu(acc[1] * inv + bb[1]));
    o[2] = __float2half(elu(acc[2] * inv + bb[2]));
    o[3] = __float2half(elu(acc[3] * inv + bb[3]));
    *(int2*)(g_out2h + (size_t)warp * C2 + colbase) = *(int2*)o;
}

// ---------------- pooling (also accumulates per-graph counts) --------------
__global__ void pool_kernel(const void* __restrict__ batch) {
    const int NPB = 200;
    int c = threadIdx.x;               // 128 threads = feature dim
    int is64 = g_is64;
    int base = blockIdx.x * NPB;
    int lim = base + NPB < NN ? base + NPB : NN;
    int cur = -1, rl = 0;
    float acc = 0.f;
    for (int n = base; n < lim; n++) {
        int g = ld_idx(batch, n, is64);
        if (g != cur) {
            if (cur >= 0) {
                atomicAdd(&g_pool[cur * C2 + c], acc);
                if (c == 0) atomicAdd(&g_counts[cur], rl);
            }
            cur = g; acc = 0.f; rl = 0;
        }
        acc += __half2float(g_out2h[(size_t)n * C2 + c]);
        rl++;
    }
    if (cur >= 0) {
        atomicAdd(&g_pool[cur * C2 + c], acc);
        if (c == 0) atomicAdd(&g_counts[cur], rl);
    }
}

__global__ void final_kernel(const float* __restrict__ lin_w, const float* __restrict__ lin_b,
                             float* __restrict__ out) {
    int t = threadIdx.x;
    if (t >= NG * NCLS) return;
    int g = t / NCLS, cls = t % NCLS;
    float cnt = fmaxf((float)g_counts[g], 1.f);
    float s = 0.f;
    for (int c = 0; c < C2; c++) s += g_pool[g * C2 + c] * lin_w[c * NCLS + cls];
    out[t] = s / cnt + lin_b[cls];
}

// ---------------- launch ----------------------------------------------------
extern "C" void kernel_launch(void* const* d_in, const int* in_sizes, int n_in,
                              void* d_out, int out_size) {
    const float* x        = (const float*)d_in[0];
    const void*  ei       = d_in[1];               // int32 or int64, detected on device
    const void*  bat      = d_in[2];
    const float* W1       = (const float*)d_in[3];
    const float* att_src1 = (const float*)d_in[4];
    const float* att_dst1 = (const float*)d_in[5];
    const float* b1       = (const float*)d_in[6];
    const float* W2       = (const float*)d_in[7];
    const float* att_src2 = (const float*)d_in[8];
    const float* att_dst2 = (const float*)d_in[9];
    const float* b2       = (const float*)d_in[10];
    const float* lin_w    = (const float*)d_in[11];
    const float* lin_b    = (const float*)d_in[12];
    float* out            = (float*)d_out;

    __half *h1h, *out1h, *h2h;
    cudaGetSymbolAddress((void**)&h1h, g_h1h);
    cudaGetSymbolAddress((void**)&out1h, g_out1h);
    cudaGetSymbolAddress((void**)&h2h, g_h2h);

    // persistent side stream + events (host resources, created once;
    // identical graph structure every call)
    static cudaStream_t s_side = nullptr;
    static cudaEvent_t s_fork = nullptr, s_join = nullptr;
    if (s_side == nullptr) {
        cudaStreamCreateWithFlags(&s_side, cudaStreamNonBlocking);
        cudaEventCreateWithFlags(&s_fork, cudaEventDisableTiming);
        cudaEventCreateWithFlags(&s_join, cudaEventDisableTiming);
    }

    // ---- fork: CSR-build branch on side stream ----
    cudaEventRecord(s_fork, 0);
    cudaStreamWaitEvent(s_side, s_fork, 0);

    prep_kernel<<<(NN + 255) / 256, 256, 0, s_side>>>((const unsigned int*)ei);
    degree_kernel<<<(ET + 255) / 256, 256, 0, s_side>>>(ei);
    scan_phase1<<<SCAN_G, SCAN_B, 0, s_side>>>();
    scan_phase2<<<1, 128, 0, s_side>>>();
    scan_phase3<<<SCAN_G, SCAN_B, 0, s_side>>>();
    scatter_kernel<<<(ET + 255) / 256, 256, 0, s_side>>>(ei);
    cudaEventRecord(s_join, s_side);

    // ---- main branch: GEMM1 (fp32 A and B converted in-register,
    //      attention coefficients fused into the epilogue) ----
    {
        dim3 grid((NN + 127) / 128, H1C1 / 128);
        hgemm128<true, true, 1><<<grid, 256>>>(x, W1, h1h, NN, H1C1, FIN, att_src1, att_dst1);
    }

    // ---- join: aggregation needs both CSR and h1 ----
    cudaStreamWaitEvent(0, s_join, 0);
    aggregate1<<<(NN * 32 + 255) / 256, 256>>>(b1);

    // layer 2: h2 = out1 @ W2 (B fp32 converted in-register, attention fused)
    {
        dim3 grid((NN + 127) / 128, C2 / 128);
        hgemm128<false, true, 2><<<grid, 256>>>(out1h, W2, h2h, NN, C2, H1C1, att_src2, att_dst2);
    }
    aggregate2<<<(NN * 32 + 255) / 256, 256>>>(b2);

    // pool + classify
    pool_kernel<<<(NN + 199) / 200, C2>>>(bat);
    final_kernel<<<1, 256>>>(lin_w, lin_b, out);
}

// round 13
// speedup vs baseline: 2.1644x; 1.0311x over previous
#include <cuda_runtime.h>
#include <cuda_fp16.h>
#include <mma.h>
#include <math.h>

using namespace nvcuda;

// Problem dims
#define NN 50000
#define EE 800000
#define ET 850000      // EE + NN self-loops
#define FIN 128
#define H1C1 256       // 4 heads * 64
#define C2 128
#define NG 32
#define NCLS 5
#define NEG_SLOPE 0.2f

#define SCAN_B 512
#define SCAN_G ((NN + SCAN_B - 1) / SCAN_B)   // 98

// ---------------- scratch (device globals; no allocations allowed) --------
__device__ __half g_h1h[(size_t)NN * H1C1];    // x @ W1  (fp16)
__device__ __half g_out1h[(size_t)NN * H1C1];  // elu(gat1) (fp16, GEMM2 input)
__device__ __half g_h2h[(size_t)NN * C2];      // out1 @ W2 (fp16)
__device__ __half g_out2h[(size_t)NN * C2];    // elu(gat2) (fp16)
__device__ float  g_asrc1[NN * 4], g_adst1[NN * 4];
__device__ float  g_asrc2[NN], g_adst2[NN];
__device__ int    g_deg[NN];
__device__ int    g_rowptr[NN + 1];
__device__ int    g_cursor[NN];
__device__ int    g_csrsrc[ET];
__device__ int    g_agg[SCAN_G];               // lookback: block aggregate
__device__ int    g_incl[SCAN_G];              // lookback: inclusive prefix
__device__ int    g_flag[SCAN_G];              // 0=none 1=agg 2=inclusive
__device__ float  g_pool[NG * C2];
__device__ int    g_counts[NG];
__device__ int    g_is64;

// ---------------- utility -------------------------------------------------
__device__ __forceinline__ float lrelu(float x) { return x > 0.f ? x : NEG_SLOPE * x; }
__device__ __forceinline__ float elu_f(float x) { return x > 0.f ? x : (__expf(x) - 1.f); }

__device__ __forceinline__ int ld_idx(const void* p, long long i, int is64) {
    if (is64) return (int)((const long long*)p)[i];
    return ((const int*)p)[i];
}

// ---------------- prep: dtype detect + zero init ---------------------------
__global__ void prep_kernel(const unsigned int* __restrict__ ei_w) {
    int i = blockIdx.x * blockDim.x + threadIdx.x;
    if (i == 0) {
        unsigned int nz = 0;
        for (int k = 0; k < 128; k++) nz |= ei_w[2 * k + 1];
        g_is64 = (nz == 0u) ? 1 : 0;
    }
    if (i < NN) g_deg[i] = 0;
    if (i < NG * C2) g_pool[i] = 0.f;
    if (i < NG) g_counts[i] = 0;
    if (i < SCAN_G) g_flag[i] = 0;
}

// ---------------- fp16 WMMA GEMM: C[M,Nn] = A[M,K] * B[K,Nn] ---------------
// Block tile 128x128, BK=32, 256 threads (8 warps: 4 M-warps x 2 N-warps),
// warp tile 32x64 (2x4 wmma 16x16x16 fragments), fp32 accumulate.
// A / B fp32 are converted in-register when AF32 / BF32. C written fp16.
// MODE 1: per-64-col-head attention dots -> g_asrc1/g_adst1 (head=by*2+p).
// MODE 2: single 128-col head -> g_asrc2/g_adst2.
#define ASTRIDE 40
#define BSTRIDE 136
#define CSTRIDE 72
template <bool AF32, bool BF32, int MODE>
__global__ __launch_bounds__(256) void hgemm128(const void* __restrict__ Ap,
                                                const void* __restrict__ Bp,
                                                __half* __restrict__ C,
                                                int M, int Nn, int K,
                                                const float* __restrict__ att_src,
                                                const float* __restrict__ att_dst) {
    __shared__ __align__(16) unsigned char smem_raw[128 * CSTRIDE * 4];
    __half* As = (__half*)smem_raw;            // 128 x ASTRIDE
    __half* Bs = As + 128 * ASTRIDE;           // 32 x BSTRIDE
    float*  St = (float*)smem_raw;             // epilogue staging 128 x CSTRIDE

    int tid = threadIdx.x;
    int wid = tid >> 5;
    int warp_m = wid & 3;
    int warp_n = wid >> 2;
    int m0 = blockIdx.x * 128, n0 = blockIdx.y * 128;

    wmma::fragment<wmma::accumulator, 16, 16, 16, float> acc[2][4];
#pragma unroll
    for (int i = 0; i < 2; i++)
#pragma unroll
        for (int j = 0; j < 4; j++) wmma::fill_fragment(acc[i][j], 0.f);

    for (int kt = 0; kt < K; kt += 32) {
#pragma unroll
        for (int u = 0; u < 2; u++) {
            int chunk = tid * 2 + u;
            int row = chunk >> 2;
            int c8 = (chunk & 3) * 8;
            if (AF32) {
                const float* A = (const float*)Ap;
                float4 v0 = make_float4(0.f, 0.f, 0.f, 0.f), v1 = v0;
                if (m0 + row < M) {
                    const float* ap = A + (size_t)(m0 + row) * K + kt + c8;
                    v0 = *(const float4*)ap;
                    v1 = *(const float4*)(ap + 4);
                }
                __half h[8] = { __float2half(v0.x), __float2half(v0.y),
                                __float2half(v0.z), __float2half(v0.w),
                                __float2half(v1.x), __float2half(v1.y),
                                __float2half(v1.z), __float2half(v1.w) };
                *(int4*)(As + row * ASTRIDE + c8) = *(int4*)h;
            } else {
                const __half* A = (const __half*)Ap;
                int4 v = make_int4(0, 0, 0, 0);
                if (m0 + row < M) v = *(const int4*)(A + (size_t)(m0 + row) * K + kt + c8);
                *(int4*)(As + row * ASTRIDE + c8) = v;
            }
        }
#pragma unroll
        for (int u = 0; u < 2; u++) {
            int chunk = tid * 2 + u;
            int row = chunk >> 4;
            int c8 = (chunk & 15) * 8;
            if (BF32) {
                const float* B = (const float*)Bp;
                const float* bp = B + (size_t)(kt + row) * Nn + n0 + c8;
                float4 v0 = *(const float4*)bp;
                float4 v1 = *(const float4*)(bp + 4);
                __half h[8] = { __float2half(v0.x), __float2half(v0.y),
                                __float2half(v0.z), __float2half(v0.w),
                                __float2half(v1.x), __float2half(v1.y),
                                __float2half(v1.z), __float2half(v1.w) };
                *(int4*)(Bs + row * BSTRIDE + c8) = *(int4*)h;
            } else {
                const __half* B = (const __half*)Bp;
                *(int4*)(Bs + row * BSTRIDE + c8) = *(const int4*)(B + (size_t)(kt + row) * Nn + n0 + c8);
            }
        }
        __syncthreads();
#pragma unroll
        for (int kk = 0; kk < 2; kk++) {
            wmma::fragment<wmma::matrix_a, 16, 16, 16, __half, wmma::row_major> af[2];
            wmma::fragment<wmma::matrix_b, 16, 16, 16, __half, wmma::row_major> bf[4];
#pragma unroll
            for (int i = 0; i < 2; i++)
                wmma::load_matrix_sync(af[i], As + (warp_m * 32 + i * 16) * ASTRIDE + kk * 16, ASTRIDE);
#pragma unroll
            for (int j = 0; j < 4; j++)
                wmma::load_matrix_sync(bf[j], Bs + (kk * 16) * BSTRIDE + warp_n * 64 + j * 16, BSTRIDE);
#pragma unroll
            for (int i = 0; i < 2; i++)
#pragma unroll
                for (int j = 0; j < 4; j++)
                    wmma::mma_sync(acc[i][j], af[i], bf[j], acc[i][j]);
        }
        __syncthreads();
    }

    // epilogue: stage fp32 frags per N-half; convert+store fp16; fused attn dots
    float sacc[4] = {0.f, 0.f, 0.f, 0.f};
    float dacc[4] = {0.f, 0.f, 0.f, 0.f};
#pragma unroll
    for (int p = 0; p < 2; p++) {
        __syncthreads();
        if (warp_n == p) {
#pragma unroll
            for (int i = 0; i < 2; i++)
#pragma unroll
                for (int j = 0; j < 4; j++)
                    wmma::store_matrix_sync(St + (warp_m * 32 + i * 16) * CSTRIDE + j * 16,
                                            acc[i][j], CSTRIDE, wmma::mem_row_major);
        }
        __syncthreads();
#pragma unroll
        for (int r = 0; r < 4; r++) {
            int row = (tid >> 3) * 4 + r;
            int col = (tid & 7) * 8;
            if (m0 + row < M) {
                const float* sp = St + row * CSTRIDE + col;
                __half h[8];
                float s = 0.f, d = 0.f;
#pragma unroll
                for (int q = 0; q < 8; q++) {
                    float v = sp[q];
                    h[q] = __float2half(v);
                    if (MODE == 1) {
                        s += v * att_src[(blockIdx.y * 2 + p) * 64 + col + q];
                        d += v * att_dst[(blockIdx.y * 2 + p) * 64 + col + q];
                    } else if (MODE == 2) {
                        s += v * att_src[p * 64 + col + q];
                        d += v * att_dst[p * 64 + col + q];
                    }
                }
                *(int4*)(C + (size_t)(m0 + row) * Nn + n0 + p * 64 + col) = *(int4*)h;
                if (MODE == 1) {
#pragma unroll
                    for (int off = 4; off; off >>= 1) {
                        s += __shfl_xor_sync(0xffffffffu, s, off);
                        d += __shfl_xor_sync(0xffffffffu, d, off);
                    }
                    if ((tid & 7) == 0) {
                        int head = blockIdx.y * 2 + p;
                        g_asrc1[(m0 + row) * 4 + head] = s;
                        g_adst1[(m0 + row) * 4 + head] = d;
                    }
                } else if (MODE == 2) {
                    sacc[r] += s;
                    dacc[r] += d;
                }
            }
        }
    }
    if (MODE == 2) {
#pragma unroll
        for (int r = 0; r < 4; r++) {
            int row = (tid >> 3) * 4 + r;
            float s = sacc[r], d = dacc[r];
#pragma unroll
            for (int off = 4; off; off >>= 1) {
                s += __shfl_xor_sync(0xffffffffu, s, off);
                d += __shfl_xor_sync(0xffffffffu, d, off);
            }
            if ((tid & 7) == 0 && m0 + row < M) {
                g_asrc2[m0 + row] = s;
                g_adst2[m0 + row] = d;
            }
        }
    }
}

// ---------------- CSR build -------------------------------------------------
__global__ void degree_kernel(const void* __restrict__ ei) {
    int e = blockIdx.x * blockDim.x + threadIdx.x;
    if (e >= ET) return;
    int is64 = g_is64;
    int d = (e < EE) ? ld_idx(ei, (long long)EE + e, is64) : (e - EE);
    atomicAdd(&g_deg[d], 1);
}

// ---- single-pass exclusive scan with decoupled lookback --------------------
// 98 blocks (all co-resident on 148 SMs -> lookback spin cannot deadlock).
__global__ void scan_fused() {
    __shared__ int sh[SCAN_B];
    __shared__ int s_prefix;
    int t = threadIdx.x, b = blockIdx.x;
    int i = b * SCAN_B + t;
    int v = (i < NN) ? g_deg[i] : 0;
    sh[t] = v;
    __syncthreads();
    // block-local inclusive scan
#pragma unroll
    for (int off = 1; off < SCAN_B; off <<= 1) {
        int u = (t >= off) ? sh[t - off] : 0;
        __syncthreads();
        sh[t] += u;
        __syncthreads();
    }
    int block_total = sh[SCAN_B - 1];

    if (t == 0) {
        volatile int* vflag = g_flag;
        volatile int* vagg  = g_agg;
        volatile int* vincl = g_incl;
        if (b == 0) {
            g_incl[0] = block_total;
            __threadfence();
            atomicExch(&g_flag[0], 2);
            s_prefix = 0;
        } else {
            g_agg[b] = block_total;
            __threadfence();
            atomicExch(&g_flag[b], 1);
            int ex = 0;
            int j = b - 1;
            while (true) {
                int f;
                do { f = vflag[j]; } while (f == 0);
                if (f == 2) { ex += vincl[j]; break; }
                ex += vagg[j];
                j--;
            }
            g_incl[b] = ex + block_total;
            __threadfence();
            atomicExch(&g_flag[b], 2);
            s_prefix = ex;
        }
    }
    __syncthreads();
    int excl = s_prefix + sh[t] - v;
    if (i < NN) {
        g_rowptr[i] = excl;
        g_cursor[i] = excl;
        if (i == NN - 1) g_rowptr[NN] = excl + v;
    }
}

__global__ void scatter_kernel(const void* __restrict__ ei) {
    int e = blockIdx.x * blockDim.x + threadIdx.x;
    if (e >= ET) return;
    int is64 = g_is64;
    int s, d;
    if (e < EE) { s = ld_idx(ei, e, is64); d = ld_idx(ei, (long long)EE + e, is64); }
    else        { s = e - EE;              d = e - EE; }
    int pos = atomicAdd(&g_cursor[d], 1);
    g_csrsrc[pos] = s;
}

// ---------------- layer-1 aggregation: warp per dst node ------------------
// Softmax stabilized with the self-loop alpha (a term of the sum, so denom>=1;
// softmax is shift-invariant, so the result is exact). 8-way unrolled for MLP.
__global__ void aggregate1(const float* __restrict__ b1) {
    int warp = (blockIdx.x * blockDim.x + threadIdx.x) >> 5;
    if (warp >= NN) return;
    int lane = threadIdx.x & 31;
    int head = lane >> 3;
    int start = g_rowptr[warp], end = g_rowptr[warp + 1];
    float ad = g_adst1[warp * 4 + head];
    float mh = lrelu(g_asrc1[warp * 4 + head] + ad);   // self-loop alpha

    float denom = 0.f;
    float acc[8] = {0.f, 0.f, 0.f, 0.f, 0.f, 0.f, 0.f, 0.f};
    int colbase = lane * 8;
    int i = start;
    for (; i + 7 < end; i += 8) {
        int sidx[8];
#pragma unroll
        for (int e = 0; e < 8; e++) sidx[e] = g_csrsrc[i + e];
        float a[8];
#pragma unroll
        for (int e = 0; e < 8; e++) a[e] = g_asrc1[sidx[e] * 4 + head];
        __half2 u[8][4];
#pragma unroll
        for (int e = 0; e < 8; e++)
            *(int4*)u[e] = *(const int4*)(g_h1h + (size_t)sidx[e] * H1C1 + colbase);
        float w[8];
#pragma unroll
        for (int e = 0; e < 8; e++) {
            w[e] = __expf(lrelu(a[e] + ad) - mh);
            denom += w[e];
        }
#pragma unroll
        for (int k = 0; k < 4; k++) {
#pragma unroll
            for (int e = 0; e < 8; e++) {
                float2 f = __half22float2(u[e][k]);
                acc[2 * k + 0] += w[e] * f.x;
                acc[2 * k + 1] += w[e] * f.y;
            }
        }
    }
    for (; i < end; i++) {
        int s0 = g_csrsrc[i];
        float w0 = __expf(lrelu(g_asrc1[s0 * 4 + head] + ad) - mh);
        denom += w0;
        __half2 u[4];
        *(int4*)u = *(const int4*)(g_h1h + (size_t)s0 * H1C1 + colbase);
#pragma unroll
        for (int k = 0; k < 4; k++) {
            float2 fu = __half22float2(u[k]);
            acc[2 * k + 0] += w0 * fu.x;
            acc[2 * k + 1] += w0 * fu.y;
        }
    }
    float inv = 1.f / (denom + 1e-16f);
    const float* bb = b1 + colbase;
    __half o[8];
#pragma unroll
    for (int k = 0; k < 8; k++) o[k] = __float2half(elu_f(acc[k] * inv + bb[k]));
    *(int4*)(g_out1h + (size_t)warp * H1C1 + colbase) = *(int4*)o;
}

// ---------------- layer-2 aggregation: warp per dst node, 1 head ----------
__global__ void aggregate2(const float* __restrict__ b2) {
    int warp = (blockIdx.x * blockDim.x + threadIdx.x) >> 5;
    if (warp >= NN) return;
    int lane = threadIdx.x & 31;
    int start = g_rowptr[warp], end = g_rowptr[warp + 1];
    float ad = g_adst2[warp];
    float m = lrelu(g_asrc2[warp] + ad);   // self-loop alpha

    float denom = 0.f;
    float acc[4] = {0.f, 0.f, 0.f, 0.f};
    int colbase = lane * 4;
    int i = start;
    for (; i + 7 < end; i += 8) {
        int sidx[8];
#pragma unroll
        for (int e = 0; e < 8; e++) sidx[e] = g_csrsrc[i + e];
        float a[8];
#pragma unroll
        for (int e = 0; e < 8; e++) a[e] = g_asrc2[sidx[e]];
        __half2 u[8][2];
#pragma unroll
        for (int e = 0; e < 8; e++)
            *(int2*)u[e] = *(const int2*)(g_h2h + (size_t)sidx[e] * C2 + colbase);
        float w[8];
#pragma unroll
        for (int e = 0; e < 8; e++) {
            w[e] = __expf(lrelu(a[e] + ad) - m);
            denom += w[e];
        }
#pragma unroll
        for (int k = 0; k < 2; k++) {
#pragma unroll
            for (int e = 0; e < 8; e++) {
                float2 f = __half22float2(u[e][k]);
                acc[2 * k + 0] += w[e] * f.x;
                acc[2 * k + 1] += w[e] * f.y;
            }
        }
    }
    for (; i < end; i++) {
        int s0 = g_csrsrc[i];
        float w0 = __expf(lrelu(g_asrc2[s0] + ad) - m);
        denom += w0;
        __half2 u[2];
        *(int2*)u = *(const int2*)(g_h2h + (size_t)s0 * C2 + colbase);
#pragma unroll
        for (int k = 0; k < 2; k++) {
            float2 fu = __half22float2(u[k]);
            acc[2 * k + 0] += w0 * fu.x;
            acc[2 * k + 1] += w0 * fu.y;
        }
    }
    float inv = 1.f / (denom + 1e-16f);
    const float* bb = b2 + colbase;
    __half o[4];
    o[0] = __float2half(elu_f(acc[0] * inv + bb[0]));
    o[1] = __float2half(elu_f(acc[1] * inv + bb[1]));
    o[2] = __float2half(elu_f(acc[2] * inv + bb[2]));
    o[3] = __float2half(elu_f(acc[3] * inv + bb[3]));
    *(int2*)(g_out2h + (size_t)warp * C2 + colbase) = *(int2*)o;
}

// ---------------- pooling (also accumulates per-graph counts) --------------
__global__ void pool_kernel(const void* __restrict__ batch) {
    const int NPB = 200;
    int c = threadIdx.x;               // 128 threads = feature dim
    int is64 = g_is64;
    int base = blockIdx.x * NPB;
    int lim = base + NPB < NN ? base + NPB : NN;
    int cur = -1, rl = 0;
    float acc = 0.f;
    for (int n = base; n < lim; n++) {
        int g = ld_idx(batch, n, is64);
        if (g != cur) {
            if (cur >= 0) {
                atomicAdd(&g_pool[cur * C2 + c], acc);
                if (c == 0) atomicAdd(&g_counts[cur], rl);
            }
            cur = g; acc = 0.f; rl = 0;
        }
        acc += __half2float(g_out2h[(size_t)n * C2 + c]);
        rl++;
    }
    if (cur >= 0) {
        atomicAdd(&g_pool[cur * C2 + c], acc);
        if (c == 0) atomicAdd(&g_counts[cur], rl);
    }
}

__global__ void final_kernel(const float* __restrict__ lin_w, const float* __restrict__ lin_b,
                             float* __restrict__ out) {
    int t = threadIdx.x;
    if (t >= NG * NCLS) return;
    int g = t / NCLS, cls = t % NCLS;
    float cnt = fmaxf((float)g_counts[g], 1.f);
    float s = 0.f;
    for (int c = 0; c < C2; c++) s += g_pool[g * C2 + c] * lin_w[c * NCLS + cls];
    out[t] = s / cnt + lin_b[cls];
}

// ---------------- launch ----------------------------------------------------
extern "C" void kernel_launch(void* const* d_in, const int* in_sizes, int n_in,
                              void* d_out, int out_size) {
    const float* x        = (const float*)d_in[0];
    const void*  ei       = d_in[1];               // int32 or int64, detected on device
    const void*  bat      = d_in[2];
    const float* W1       = (const float*)d_in[3];
    const float* att_src1 = (const float*)d_in[4];
    const float* att_dst1 = (const float*)d_in[5];
    const float* b1       = (const float*)d_in[6];
    const float* W2       = (const float*)d_in[7];
    const float* att_src2 = (const float*)d_in[8];
    const float* att_dst2 = (const float*)d_in[9];
    const float* b2       = (const float*)d_in[10];
    const float* lin_w    = (const float*)d_in[11];
    const float* lin_b    = (const float*)d_in[12];
    float* out            = (float*)d_out;

    __half *h1h, *out1h, *h2h;
    cudaGetSymbolAddress((void**)&h1h, g_h1h);
    cudaGetSymbolAddress((void**)&out1h, g_out1h);
    cudaGetSymbolAddress((void**)&h2h, g_h2h);

    // persistent side stream + events (host resources, created once;
    // identical graph structure every call)
    static cudaStream_t s_side = nullptr;
    static cudaEvent_t s_fork = nullptr, s_join = nullptr;
    if (s_side == nullptr) {
        cudaStreamCreateWithFlags(&s_side, cudaStreamNonBlocking);
        cudaEventCreateWithFlags(&s_fork, cudaEventDisableTiming);
        cudaEventCreateWithFlags(&s_join, cudaEventDisableTiming);
    }

    // ---- fork: CSR-build branch on side stream ----
    cudaEventRecord(s_fork, 0);
    cudaStreamWaitEvent(s_side, s_fork, 0);

    prep_kernel<<<(NN + 255) / 256, 256, 0, s_side>>>((const unsigned int*)ei);
    degree_kernel<<<(ET + 255) / 256, 256, 0, s_side>>>(ei);
    scan_fused<<<SCAN_G, SCAN_B, 0, s_side>>>();
    scatter_kernel<<<(ET + 255) / 256, 256, 0, s_side>>>(ei);
    cudaEventRecord(s_join, s_side);

    // ---- main branch: GEMM1 (fp32 A and B converted in-register,
    //      attention coefficients fused into the epilogue) ----
    {
        dim3 grid((NN + 127) / 128, H1C1 / 128);
        hgemm128<true, true, 1><<<grid, 256>>>(x, W1, h1h, NN, H1C1, FIN, att_src1, att_dst1);
    }

    // ---- join: aggregation needs both CSR and h1 ----
    cudaStreamWaitEvent(0, s_join, 0);
    aggregate1<<<(NN * 32 + 255) / 256, 256>>>(b1);

    // layer 2: h2 = out1 @ W2 (B fp32 converted in-register, attention fused)
    {
        dim3 grid((NN + 127) / 128, C2 / 128);
        hgemm128<false, true, 2><<<grid, 256>>>(out1h, W2, h2h, NN, C2, H1C1, att_src2, att_dst2);
    }
    aggregate2<<<(NN * 32 + 255) / 256, 256>>>(b2);

    // pool + classify
    pool_kernel<<<(NN + 199) / 200, C2>>>(bat);
    final_kernel<<<1, 256>>>(lin_w, lin_b, out);
}